// round 10
// baseline (speedup 1.0000x reference)
#include <cuda_runtime.h>
#include <cuda_bf16.h>

#define EMBED 1024
#define NHEADS 16
#define HDIM 64
#define SEQ 2048
#define NCLS 1000
#define GCHUNKS 8
#define MTOT 4096

#define BM 128
#define BN 128
#define PKB 144                 // padded row bytes (both gemm kernels)
#define ATILE (128 * PKB)       // 18432
#define STAGE (2 * ATILE)       // 36864  {A,B}
#define SMEMB (2 * STAGE)       // 73728 -> 2 CTAs/SM
#define NITM 16                 // main: K=1024 / 64 bf16
#define NITC 16                 // corr: K'=2048 / 128 int8

// quant scales (powers of 2); sAh*sBl == sAl*sBh per GEMM
#define SX_H 16.0f              // x hi
#define SX_L 8192.0f            // x lo (2^13)
#define SW_H 4096.0f            // W hi (2^12)
#define SW_L 2097152.0f         // W lo (2^21)
#define SCALE1 (1.0f / 33554432.0f)   // 2^-25
#define SP_H 16.0f
#define SP_L 8192.0f
#define SB2_H 32.0f             // 2^5
#define SB2_L 16384.0f          // 2^14
#define SCALE2 (1.0f / 262144.0f)     // 2^-18

// ---------- scratch ----------
__device__ float g_G[32 * HDIM * HDIM];
__device__ float g_Gpart[GCHUNKS][32][HDIM * HDIM];
__device__ float g_Cmain[MTOT * 1024];
__device__ __nv_bfloat16 g_xh[MTOT * EMBED];
__device__ __nv_bfloat16 g_wih[EMBED * EMBED];
__device__ __nv_bfloat16 g_ph[MTOT * EMBED], g_pl[MTOT * EMBED];
__device__ __nv_bfloat16 g_b2h[2 * 1024 * EMBED];
__device__ char g_Xcat[MTOT * 2048];
__device__ char g_Wcat[1024 * 2048];
__device__ char g_Pcat[MTOT * 2048];
__device__ char g_B2cat[2 * 1024 * 2048];

// ---------- helpers ----------
__device__ __forceinline__ unsigned smem_u32(const void* p) {
    unsigned a;
    asm("{ .reg .u64 t; cvta.to.shared.u64 t, %1; cvt.u32.u64 %0, t; }" : "=r"(a) : "l"(p));
    return a;
}
__device__ __forceinline__ void cpa16(unsigned s, const void* g) {
    asm volatile("cp.async.cg.shared.global [%0], [%1], 16;" :: "r"(s), "l"(g) : "memory");
}
#define CP_COMMIT() asm volatile("cp.async.commit_group;" ::: "memory")
#define CP_WAIT(n)  asm volatile("cp.async.wait_group %0;" :: "n"(n) : "memory")

#define LDSM4(r0, r1, r2, r3, a) \
    asm volatile("ldmatrix.sync.aligned.m8n8.x4.shared.b16 {%0,%1,%2,%3}, [%4];" \
        : "=r"(r0), "=r"(r1), "=r"(r2), "=r"(r3) : "r"(a))

#define LDSM4T(r0, r1, r2, r3, a) \
    asm volatile("ldmatrix.sync.aligned.m8n8.x4.trans.shared.b16 {%0,%1,%2,%3}, [%4];" \
        : "=r"(r0), "=r"(r1), "=r"(r2), "=r"(r3) : "r"(a))

#define MMA(c, a, b0v, b1v) \
    asm volatile("mma.sync.aligned.m16n8k16.row.col.f32.bf16.bf16.f32 " \
        "{%0,%1,%2,%3},{%4,%5,%6,%7},{%8,%9},{%0,%1,%2,%3};" \
        : "+f"((c)[0]), "+f"((c)[1]), "+f"((c)[2]), "+f"((c)[3]) \
        : "r"((a)[0]), "r"((a)[1]), "r"((a)[2]), "r"((a)[3]), "r"(b0v), "r"(b1v))

#define MMAS8(c, a, b0v, b1v) \
    asm volatile("mma.sync.aligned.m16n8k32.row.col.s32.s8.s8.s32 " \
        "{%0,%1,%2,%3},{%4,%5,%6,%7},{%8,%9},{%0,%1,%2,%3};" \
        : "+r"((c)[0]), "+r"((c)[1]), "+r"((c)[2]), "+r"((c)[3]) \
        : "r"((a)[0]), "r"((a)[1]), "r"((a)[2]), "r"((a)[3]), "r"(b0v), "r"(b1v))

__device__ __forceinline__ unsigned pack_bf(float e0, float e1) {
    unsigned r;
    asm("cvt.rn.bf16x2.f32 %0, %1, %2;" : "=r"(r) : "f"(e1), "f"(e0));
    return r;
}
__device__ __forceinline__ int q8(float v, float s) {
    int t = __float2int_rn(v * s);
    return t > 127 ? 127 : (t < -127 ? -127 : t);
}

// ---------- cvt: fp32 -> hi bf16 + int8 cat halves ----------
// rows are 1024 fp32 wide; Cat rows 2048 int8. hiFirst=1 -> [hi|lo] else [lo|hi].
__global__ void cvt_q(const float4* __restrict__ X, uint2* __restrict__ H,
                      char* __restrict__ Cat, int n4, float sHi, float sLo, int hiFirst)
{
    int i = blockIdx.x * blockDim.x + threadIdx.x;
    if (i >= n4) return;
    float4 x = X[i];
    unsigned h01 = pack_bf(x.x, x.y), h23 = pack_bf(x.z, x.w);
    float hx = __uint_as_float(h01 << 16), hy = __uint_as_float(h01 & 0xffff0000u);
    float hz = __uint_as_float(h23 << 16), hw = __uint_as_float(h23 & 0xffff0000u);
    H[i] = make_uint2(h01, h23);
    char4 hq = make_char4(q8(hx, sHi), q8(hy, sHi), q8(hz, sHi), q8(hw, sHi));
    char4 lq = make_char4(q8(x.x - hx, sLo), q8(x.y - hy, sLo),
                          q8(x.z - hz, sLo), q8(x.w - hw, sLo));
    size_t base = (size_t)(i >> 8) * 2048 + (size_t)(i & 255) * 4;
    *(char4*)(Cat + base + (hiFirst ? 0 : 1024)) = hq;
    *(char4*)(Cat + base + (hiFirst ? 1024 : 0)) = lq;
}

// ---------- main bf16 GEMM (hi terms only): Cm[M][1024] = Ah @ Bh^T ----------
__device__ __forceinline__ void load_m(
    unsigned sbuf, int tid, int k0,
    const __nv_bfloat16* A, const __nv_bfloat16* B, int m0, int n0)
{
    int row = tid >> 1, h = tid & 1;
    unsigned soff = (unsigned)(row * PKB + h * 64);
    size_t ga = (size_t)(m0 + row) * EMBED + k0 + h * 32;
    size_t gb = (size_t)(n0 + row) * EMBED + k0 + h * 32;
#pragma unroll
    for (int g = 0; g < 4; g++) {
        cpa16(sbuf + soff + g * 16,         A + ga + g * 8);
        cpa16(sbuf + ATILE + soff + g * 16, B + gb + g * 8);
    }
}

__global__ __launch_bounds__(256, 2) void gemm_main_bf16(
    const __nv_bfloat16* __restrict__ A, const __nv_bfloat16* __restrict__ Bbase,
    long bStride, float* __restrict__ Cm)
{
    extern __shared__ char smc[];
    int tid = threadIdx.x;
    int m0 = blockIdx.y * BM, n0 = blockIdx.x * BN;
    unsigned sbase = smem_u32(smc);
    const __nv_bfloat16* B = Bbase + (size_t)(m0 >> 11) * bStride;

    int wid = tid >> 5, lane = tid & 31;
    int wm = (wid & 1) * 64, wn = (wid >> 1) * 32;

    float acc[4][4][4];
#pragma unroll
    for (int i = 0; i < 4; i++)
#pragma unroll
        for (int j = 0; j < 4; j++)
#pragma unroll
            for (int v = 0; v < 4; v++) acc[i][j][v] = 0.f;

    load_m(sbase, tid, 0, A, B, m0, n0);
    CP_COMMIT();

    unsigned a_lo = (unsigned)((wm + (lane & 15)) * PKB + (lane >> 4) * 16);
    unsigned b_lo = (unsigned)(ATILE + (wn + (lane & 15)) * PKB + (lane >> 4) * 16);

    for (int it = 0; it < NITM; it++) {
        CP_WAIT(0);
        __syncthreads();
        if (it + 1 < NITM) {
            load_m(sbase + (unsigned)((it + 1) & 1) * STAGE, tid, (it + 1) * 64, A, B, m0, n0);
            CP_COMMIT();
        }
        unsigned sbuf = sbase + (unsigned)(it & 1) * STAGE;
#pragma unroll
        for (int ks = 0; ks < 4; ks++) {
            unsigned ah[4][4], bb[2][4];
            unsigned ao = sbuf + a_lo + (unsigned)ks * 32;
            unsigned bo = sbuf + b_lo + (unsigned)ks * 32;
#pragma unroll
            for (int i = 0; i < 4; i++)
                LDSM4(ah[i][0], ah[i][1], ah[i][2], ah[i][3], ao + (unsigned)i * (16 * PKB));
#pragma unroll
            for (int L = 0; L < 2; L++)
                LDSM4(bb[L][0], bb[L][1], bb[L][2], bb[L][3], bo + (unsigned)L * (16 * PKB));
#pragma unroll
            for (int i = 0; i < 4; i++)
#pragma unroll
                for (int j = 0; j < 4; j++) {
                    int L = j >> 1, s = j & 1;
                    MMA(acc[i][j], ah[i], bb[L][s], bb[L][s + 2]);
                }
        }
    }

    int r = lane >> 2, c2 = (lane & 3) * 2;
#pragma unroll
    for (int i = 0; i < 4; i++) {
        int m = m0 + wm + i * 16 + r;
        float* C0 = Cm + (size_t)m * 1024;
        float* C1 = C0 + 8 * 1024;
#pragma unroll
        for (int j = 0; j < 4; j++) {
            int n = n0 + wn + j * 8 + c2;
            float2 v0 = make_float2(acc[i][j][0], acc[i][j][1]);
            float2 v1 = make_float2(acc[i][j][2], acc[i][j][3]);
            *(float2*)(C0 + n) = v0;
            *(float2*)(C1 + n) = v1;
        }
    }
}

// ---------- s8 correction GEMM + final epilogue ----------
// cross = Acat[M][2048] @ Bcat[1024][2048]^T (s32); v = Cm + cross*scale + bias.
// outF!=null: write out[m][n] (n<Nout). else: write ph/pl bf16 + Pcat int8.
__device__ __forceinline__ void load_c(
    unsigned sbuf, int tid, int k0,
    const char* A, const char* B, int m0, int n0)
{
    int row = tid >> 1, h = tid & 1;
    unsigned soff = (unsigned)(row * PKB + h * 64);
    size_t ga = (size_t)(m0 + row) * 2048 + k0 + h * 64;
    size_t gb = (size_t)(n0 + row) * 2048 + k0 + h * 64;
#pragma unroll
    for (int g = 0; g < 4; g++) {
        cpa16(sbuf + soff + g * 16,         A + ga + g * 16);
        cpa16(sbuf + ATILE + soff + g * 16, B + gb + g * 16);
    }
}

__global__ __launch_bounds__(256, 2) void gemm_corr_s8(
    const char* __restrict__ Acat, const char* __restrict__ BcatBase, long bStride,
    const float* __restrict__ Cm, const float* __restrict__ bias, float scale,
    float* __restrict__ outF, int Nout,
    __nv_bfloat16* __restrict__ Ph, __nv_bfloat16* __restrict__ Pl, char* __restrict__ Pcat)
{
    extern __shared__ char smc[];
    int tid = threadIdx.x;
    int m0 = blockIdx.y * BM, n0 = blockIdx.x * BN;
    unsigned sbase = smem_u32(smc);
    const char* B = BcatBase + (size_t)(m0 >> 11) * bStride;

    int wid = tid >> 5, lane = tid & 31;
    int wm = (wid & 1) * 64, wn = (wid >> 1) * 32;

    int acc[4][4][4];
#pragma unroll
    for (int i = 0; i < 4; i++)
#pragma unroll
        for (int j = 0; j < 4; j++)
#pragma unroll
            for (int v = 0; v < 4; v++) acc[i][j][v] = 0;

    load_c(sbase, tid, 0, Acat, B, m0, n0);
    CP_COMMIT();

    unsigned a_lo = (unsigned)((wm + (lane & 15)) * PKB + (lane >> 4) * 16);
    unsigned b_lo = (unsigned)(ATILE + (wn + (lane & 15)) * PKB + (lane >> 4) * 16);

    for (int it = 0; it < NITC; it++) {
        CP_WAIT(0);
        __syncthreads();
        if (it + 1 < NITC) {
            load_c(sbase + (unsigned)((it + 1) & 1) * STAGE, tid, (it + 1) * 128, Acat, B, m0, n0);
            CP_COMMIT();
        }
        unsigned sbuf = sbase + (unsigned)(it & 1) * STAGE;
#pragma unroll
        for (int ks = 0; ks < 4; ks++) {
            unsigned ah[4][4], bb[2][4];
            unsigned ao = sbuf + a_lo + (unsigned)ks * 32;
            unsigned bo = sbuf + b_lo + (unsigned)ks * 32;
#pragma unroll
            for (int i = 0; i < 4; i++)
                LDSM4(ah[i][0], ah[i][1], ah[i][2], ah[i][3], ao + (unsigned)i * (16 * PKB));
#pragma unroll
            for (int L = 0; L < 2; L++)
                LDSM4(bb[L][0], bb[L][1], bb[L][2], bb[L][3], bo + (unsigned)L * (16 * PKB));
#pragma unroll
            for (int i = 0; i < 4; i++)
#pragma unroll
                for (int j = 0; j < 4; j++) {
                    int L = j >> 1, s = j & 1;
                    MMAS8(acc[i][j], ah[i], bb[L][s], bb[L][s + 2]);
                }
        }
    }

    int r = lane >> 2, c2 = (lane & 3) * 2;
#pragma unroll
    for (int i = 0; i < 4; i++) {
        int m = m0 + wm + i * 16 + r;
#pragma unroll
        for (int j = 0; j < 4; j++) {
            int n = n0 + wn + j * 8 + c2;
            float2 cm0 = *(const float2*)(Cm + (size_t)m * 1024 + n);
            float2 cm1 = *(const float2*)(Cm + (size_t)(m + 8) * 1024 + n);
            float b0 = (n < Nout) ? bias[n] : 0.f;
            float b1 = (n + 1 < Nout) ? bias[n + 1] : 0.f;
            float v00 = cm0.x + scale * (float)acc[i][j][0] + b0;
            float v01 = cm0.y + scale * (float)acc[i][j][1] + b1;
            float v10 = cm1.x + scale * (float)acc[i][j][2] + b0;
            float v11 = cm1.y + scale * (float)acc[i][j][3] + b1;
            if (outF) {
                if (n < Nout) {
                    outF[(size_t)m * Nout + n] = v00;
                    outF[(size_t)(m + 8) * Nout + n] = v10;
                }
                if (n + 1 < Nout) {
                    outF[(size_t)m * Nout + n + 1] = v01;
                    outF[(size_t)(m + 8) * Nout + n + 1] = v11;
                }
            } else {
#pragma unroll
                for (int rr = 0; rr < 2; rr++) {
                    int mm = m + rr * 8;
                    float e0 = rr ? v10 : v00, e1 = rr ? v11 : v01;
                    unsigned hp = pack_bf(e0, e1);
                    float hx = __uint_as_float(hp << 16);
                    float hy = __uint_as_float(hp & 0xffff0000u);
                    *(unsigned*)(Ph + (size_t)mm * EMBED + n) = hp;
                    *(unsigned*)(Pl + (size_t)mm * EMBED + n) = pack_bf(e0 - hx, e1 - hy);
                    char2 hq = make_char2((char)q8(hx, SP_H), (char)q8(hy, SP_H));
                    char2 lq = make_char2((char)q8(e0 - hx, SP_L), (char)q8(e1 - hy, SP_L));
                    *(char2*)(Pcat + (size_t)mm * 2048 + n) = hq;
                    *(char2*)(Pcat + (size_t)mm * 2048 + 1024 + n) = lq;
                }
            }
        }
    }
}

// ---------- tensor-core Gram (unchanged from R9) ----------
#define GPD 72

__global__ __launch_bounds__(256, 2) void head_gram_mma(
    const __nv_bfloat16* __restrict__ ph, const __nv_bfloat16* __restrict__ pl,
    float* __restrict__ Gpart)
{
    __shared__ __nv_bfloat16 sh[128][GPD];
    __shared__ __nv_bfloat16 sl[128][GPD];

    int bh = blockIdx.x, chunk = blockIdx.y;
    int b = bh >> 4, h = bh & 15;
    int tid = threadIdx.x;
    int wid = tid >> 5, lane = tid & 31;
    int wm = (wid & 1) * 32, wn = (wid >> 1) * 16;

    unsigned shB = smem_u32(&sh[0][0]);
    unsigned slB = smem_u32(&sl[0][0]);

    int g = lane >> 3, l = lane & 7;
    unsigned aRowOff = (unsigned)(((g & 2) ? 8 : 0) + l) * (GPD * 2);
    unsigned aColOff = (unsigned)(wm + ((g & 1) ? 8 : 0)) * 2;
    unsigned bRowOff = (unsigned)(((g & 1) ? 8 : 0) + l) * (GPD * 2);
    unsigned bColOff = (unsigned)(wn + ((g >= 2) ? 8 : 0)) * 2;

    float acc[2][2][4];
#pragma unroll
    for (int i = 0; i < 2; i++)
#pragma unroll
        for (int j = 0; j < 2; j++)
#pragma unroll
            for (int v = 0; v < 4; v++) acc[i][j][v] = 0.f;

    int row = tid >> 1, q = tid & 1;
    unsigned soff = (unsigned)(row * GPD + q * 32) * 2;

    for (int half = 0; half < 2; half++) {
        size_t gbase = (size_t)(b * SEQ + chunk * 256 + half * 128 + row) * EMBED + h * HDIM + q * 32;
#pragma unroll
        for (int t = 0; t < 4; t++) {
            cpa16(shB + soff + t * 16, ph + gbase + t * 8);
            cpa16(slB + soff + t * 16, pl + gbase + t * 8);
        }
        CP_COMMIT();
        CP_WAIT(0);
        __syncthreads();

#pragma unroll
        for (int k0 = 0; k0 < 128; k0 += 16) {
            unsigned kb = (unsigned)k0 * (GPD * 2);
            unsigned Ah2[2][4], Al2[2][4], Bh4[4], Bl4[4];
#pragma unroll
            for (int i = 0; i < 2; i++) {
                LDSM4T(Ah2[i][0], Ah2[i][1], Ah2[i][2], Ah2[i][3],
                       shB + kb + aRowOff + aColOff + (unsigned)i * 32);
                LDSM4T(Al2[i][0], Al2[i][1], Al2[i][2], Al2[i][3],
                       slB + kb + aRowOff + aColOff + (unsigned)i * 32);
            }
            LDSM4T(Bh4[0], Bh4[1], Bh4[2], Bh4[3], shB + kb + bRowOff + bColOff);
            LDSM4T(Bl4[0], Bl4[1], Bl4[2], Bl4[3], slB + kb + bRowOff + bColOff);

#pragma unroll
            for (int i = 0; i < 2; i++)
#pragma unroll
                for (int j = 0; j < 2; j++) {
                    MMA(acc[i][j], Ah2[i], Bh4[j * 2], Bh4[j * 2 + 1]);
                    MMA(acc[i][j], Ah2[i], Bl4[j * 2], Bl4[j * 2 + 1]);
                    MMA(acc[i][j], Al2[i], Bh4[j * 2], Bh4[j * 2 + 1]);
                }
        }
        __syncthreads();
    }

    float* Gp = Gpart + ((size_t)chunk * 32 + bh) * (HDIM * HDIM);
    int r = lane >> 2, c2 = (lane & 3) * 2;
#pragma unroll
    for (int i = 0; i < 2; i++) {
        int d1a = wm + i * 16 + r;
#pragma unroll
        for (int j = 0; j < 2; j++) {
            int d2 = wn + j * 8 + c2;
            Gp[d1a * HDIM + d2]           = acc[i][j][0];
            Gp[d1a * HDIM + d2 + 1]       = acc[i][j][1];
            Gp[(d1a + 8) * HDIM + d2]     = acc[i][j][2];
            Gp[(d1a + 8) * HDIM + d2 + 1] = acc[i][j][3];
        }
    }
}

__global__ void gram_reduce(const float* __restrict__ Gpart,
                            float* __restrict__ G, float scale)
{
    int idx = blockIdx.x * blockDim.x + threadIdx.x;
    if (idx >= 32 * HDIM * HDIM) return;
    float s = 0.f;
#pragma unroll
    for (int c = 0; c < GCHUNKS; c++)
        s += Gpart[(size_t)c * 32 * HDIM * HDIM + idx];
    G[idx] = s * scale;
}

// ---------- fused B2 build: bf16 hi + int8 cat ----------
__global__ __launch_bounds__(256) void w2_build(
    const float* __restrict__ Wo, const float* __restrict__ G,
    __nv_bfloat16* __restrict__ B2h, char* __restrict__ B2cat)
{
    int c0 = blockIdx.x * 64;
    int h  = blockIdx.y;
    int b  = blockIdx.z;
    const float* Gh = G + (size_t)(b * NHEADS + h) * HDIM * HDIM;

    __shared__ float Gs[64][65];
    __shared__ float Ws[64][65];
    int tid = threadIdx.x;

#pragma unroll
    for (int v = 0; v < 4; v++) {
        int idx = tid + v * 256;
        int rr = idx >> 4;
        int c = (idx & 15) << 2;
        float4 g4 = *(const float4*)(Gh + rr * HDIM + c);
        Gs[rr][c + 0] = g4.x; Gs[rr][c + 1] = g4.y;
        Gs[rr][c + 2] = g4.z; Gs[rr][c + 3] = g4.w;
        float4 w4 = make_float4(0.f, 0.f, 0.f, 0.f);
        if (c0 + rr < NCLS)
            w4 = *(const float4*)(Wo + (size_t)(c0 + rr) * EMBED + h * HDIM + c);
        Ws[rr][c + 0] = w4.x; Ws[rr][c + 1] = w4.y;
        Ws[rr][c + 2] = w4.z; Ws[rr][c + 3] = w4.w;
    }
    __syncthreads();

    int j  = tid & 63;
    int i0 = (tid >> 6) << 4;
    float acc[16];
#pragma unroll
    for (int ii = 0; ii < 16; ii++) acc[ii] = 0.f;

#pragma unroll 4
    for (int k = 0; k < 64; k++) {
        float g = Gs[k][j];
#pragma unroll
        for (int ii = 0; ii < 16; ii++)
            acc[ii] += Ws[i0 + ii][k] * g;
    }

#pragma unroll
    for (int ii = 0; ii < 16; ii++) {
        int c = c0 + i0 + ii;
        int k = h * HDIM + j;
        float v = acc[ii];
        __nv_bfloat16 hi = __float2bfloat16(v);
        float hif = __bfloat162float(hi);
        B2h[(size_t)b * 1024 * EMBED + (size_t)c * EMBED + k] = hi;
        size_t cb = (size_t)b * 1024 * 2048 + (size_t)c * 2048;
        B2cat[cb + k]        = (char)q8(v - hif, SB2_L);   // lo first
        B2cat[cb + 1024 + k] = (char)q8(hif, SB2_H);
    }
}

// ---------- launch ----------
extern "C" void kernel_launch(void* const* d_in, const int* in_sizes, int n_in,
                              void* d_out, int out_size)
{
    const float* x     = (const float*)d_in[0];
    const float* W_in  = (const float*)d_in[1];
    const float* b_in  = (const float*)d_in[2];
    const float* W_out = (const float*)d_in[3];
    const float* b_out = (const float*)d_in[4];
    float* out = (float*)d_out;

    int M = in_sizes[0] / EMBED;   // 4096

    float *G, *Gp, *Cm;
    cudaGetSymbolAddress((void**)&G, g_G);
    cudaGetSymbolAddress((void**)&Gp, g_Gpart);
    cudaGetSymbolAddress((void**)&Cm, g_Cmain);
    __nv_bfloat16 *xh, *wih, *ph, *pl, *b2h;
    cudaGetSymbolAddress((void**)&xh, g_xh);
    cudaGetSymbolAddress((void**)&wih, g_wih);
    cudaGetSymbolAddress((void**)&ph, g_ph);
    cudaGetSymbolAddress((void**)&pl, g_pl);
    cudaGetSymbolAddress((void**)&b2h, g_b2h);
    char *Xcat, *Wcat, *Pcat, *B2cat;
    cudaGetSymbolAddress((void**)&Xcat, g_Xcat);
    cudaGetSymbolAddress((void**)&Wcat, g_Wcat);
    cudaGetSymbolAddress((void**)&Pcat, g_Pcat);
    cudaGetSymbolAddress((void**)&B2cat, g_B2cat);

    cudaFuncSetAttribute(gemm_main_bf16, cudaFuncAttributeMaxDynamicSharedMemorySize, SMEMB);
    cudaFuncSetAttribute(gemm_corr_s8,   cudaFuncAttributeMaxDynamicSharedMemorySize, SMEMB);

    dim3 blk(256);
    dim3 ggrid(1024 / BN, M / BM);   // (8, 32)

    // quantize inputs: x -> [hi|lo], W -> [lo|hi]
    cvt_q<<<(M * EMBED / 4) / 256, blk>>>((const float4*)x, (uint2*)xh, Xcat,
                                          M * EMBED / 4, SX_H, SX_L, 1);
    cvt_q<<<(EMBED * EMBED / 4) / 256, blk>>>((const float4*)W_in, (uint2*)wih, Wcat,
                                              EMBED * EMBED / 4, SW_H, SW_L, 0);

    // 1) P: main bf16 + s8 correction (epilogue -> ph, pl, Pcat; bias b_in)
    gemm_main_bf16<<<ggrid, blk, SMEMB>>>(xh, wih, 0, Cm);
    gemm_corr_s8<<<ggrid, blk, SMEMB>>>(Xcat, Wcat, 0, Cm, b_in, SCALE1,
                                        nullptr, 1024, ph, pl, Pcat);

    // 2) G = (1/32) * P_h^T P_h
    head_gram_mma<<<dim3(32, GCHUNKS), blk>>>(ph, pl, Gp);
    gram_reduce<<<(32 * HDIM * HDIM + 255) / 256, blk>>>(Gp, G, 1.0f / 32.0f);

    // 3) B2[b] = blockdiag(G) @ W_out^T  -> b2h bf16 + B2cat int8
    w2_build<<<dim3(1024 / 64, NHEADS, M / SEQ), blk>>>(W_out, G, b2h, B2cat);

    // 4) out: main bf16 + s8 correction (bias b_out, N=1000)
    gemm_main_bf16<<<ggrid, blk, SMEMB>>>(ph, b2h, (long)1024 * EMBED, Cm);
    gemm_corr_s8<<<ggrid, blk, SMEMB>>>(Pcat, B2cat, (long)1024 * 2048, Cm, b_out, SCALE2,
                                        out, NCLS, nullptr, nullptr, nullptr);
}

// round 11
// speedup vs baseline: 1.7950x; 1.7950x over previous
#include <cuda_runtime.h>
#include <cuda_bf16.h>

#define EMBED 1024
#define NHEADS 16
#define HDIM 64
#define SEQ 2048
#define NCLS 1000
#define GCHUNKS 16
#define MTOT 4096

#define BM 128
#define BN 128
#define BKE 32
#define NIT (EMBED / BKE)         // 32
#define PK 40                     // padded row: 80B, ldmatrix conflict-free
#define TSZ (BM * PK)
#define STAGEB (4 * TSZ * 2)      // 40960 B
#define SMEM_BYTES (2 * STAGEB)   // 81920 -> 2 CTAs/SM

// ---------- scratch ----------
__device__ float g_G[32 * HDIM * HDIM];
__device__ float g_Gpart[GCHUNKS][32][HDIM * HDIM];
__device__ __nv_bfloat16 g_xh[MTOT * EMBED], g_xl[MTOT * EMBED];
__device__ __nv_bfloat16 g_wih[EMBED * EMBED], g_wil[EMBED * EMBED];
__device__ __nv_bfloat16 g_ph[MTOT * EMBED], g_pl[MTOT * EMBED];
__device__ __nv_bfloat16 g_b2h[2 * 1024 * EMBED], g_b2l[2 * 1024 * EMBED];

// ---------- helpers ----------
__device__ __forceinline__ unsigned smem_u32(const void* p) {
    unsigned a;
    asm("{ .reg .u64 t; cvta.to.shared.u64 t, %1; cvt.u32.u64 %0, t; }" : "=r"(a) : "l"(p));
    return a;
}
__device__ __forceinline__ void cpa16(unsigned s, const void* g) {
    asm volatile("cp.async.cg.shared.global [%0], [%1], 16;" :: "r"(s), "l"(g) : "memory");
}
#define CP_COMMIT() asm volatile("cp.async.commit_group;" ::: "memory")
#define CP_WAIT(n)  asm volatile("cp.async.wait_group %0;" :: "n"(n) : "memory")

#define LDSM4(r0, r1, r2, r3, a) \
    asm volatile("ldmatrix.sync.aligned.m8n8.x4.shared.b16 {%0,%1,%2,%3}, [%4];" \
        : "=r"(r0), "=r"(r1), "=r"(r2), "=r"(r3) : "r"(a))

#define LDSM4T(r0, r1, r2, r3, a) \
    asm volatile("ldmatrix.sync.aligned.m8n8.x4.trans.shared.b16 {%0,%1,%2,%3}, [%4];" \
        : "=r"(r0), "=r"(r1), "=r"(r2), "=r"(r3) : "r"(a))

#define MMA(c, a, b0v, b1v) \
    asm volatile("mma.sync.aligned.m16n8k16.row.col.f32.bf16.bf16.f32 " \
        "{%0,%1,%2,%3},{%4,%5,%6,%7},{%8,%9},{%0,%1,%2,%3};" \
        : "+f"((c)[0]), "+f"((c)[1]), "+f"((c)[2]), "+f"((c)[3]) \
        : "r"((a)[0]), "r"((a)[1]), "r"((a)[2]), "r"((a)[3]), "r"(b0v), "r"(b1v))

__device__ __forceinline__ unsigned pack_bf(float e0, float e1) {
    unsigned r;
    asm("cvt.rn.bf16x2.f32 %0, %1, %2;" : "=r"(r) : "f"(e1), "f"(e0));
    return r;
}

// ---------- fp32 -> (hi, lo) bf16 split ----------
__global__ void cvt_split(const float4* __restrict__ X, uint2* __restrict__ H,
                          uint2* __restrict__ L, int n4) {
    int i = blockIdx.x * blockDim.x + threadIdx.x;
    if (i >= n4) return;
    float4 x = X[i];
    unsigned h01 = pack_bf(x.x, x.y), h23 = pack_bf(x.z, x.w);
    float hx = __uint_as_float(h01 << 16), hy = __uint_as_float(h01 & 0xffff0000u);
    float hz = __uint_as_float(h23 << 16), hw = __uint_as_float(h23 & 0xffff0000u);
    unsigned l01 = pack_bf(x.x - hx, x.y - hy), l23 = pack_bf(x.z - hz, x.w - hw);
    H[i] = make_uint2(h01, h23);
    L[i] = make_uint2(l01, l23);
}

// ---------- bf16x3 mma.sync GEMM ----------
__device__ __forceinline__ void load_stage(
    unsigned sbuf, int tid, int k0,
    const __nv_bfloat16* Ah, const __nv_bfloat16* Al,
    const __nv_bfloat16* Bh, const __nv_bfloat16* Bl,
    int m0, int n0)
{
    int row = tid >> 1;
    int half = tid & 1;
    unsigned soff = (unsigned)(row * PK + half * 16) * 2;
    size_t ga = (size_t)(m0 + row) * EMBED + k0 + half * 16;
    size_t gb = (size_t)(n0 + row) * EMBED + k0 + half * 16;
    cpa16(sbuf + soff,                Ah + ga);
    cpa16(sbuf + soff + 16,           Ah + ga + 8);
    cpa16(sbuf + TSZ * 2 + soff,      Al + ga);
    cpa16(sbuf + TSZ * 2 + soff + 16, Al + ga + 8);
    cpa16(sbuf + TSZ * 4 + soff,      Bh + gb);
    cpa16(sbuf + TSZ * 4 + soff + 16, Bh + gb + 8);
    cpa16(sbuf + TSZ * 6 + soff,      Bl + gb);
    cpa16(sbuf + TSZ * 6 + soff + 16, Bl + gb + 8);
}

__global__ __launch_bounds__(256, 2) void gemm_mma_bf16x3(
    const __nv_bfloat16* __restrict__ Ah, const __nv_bfloat16* __restrict__ Al,
    const __nv_bfloat16* __restrict__ BhBase, const __nv_bfloat16* __restrict__ BlBase,
    const float* __restrict__ bias, float* __restrict__ C,
    __nv_bfloat16* __restrict__ Sh, __nv_bfloat16* __restrict__ Sl,
    int N, long bStride)
{
    extern __shared__ __nv_bfloat16 sm[];
    int tid = threadIdx.x;
    int m0 = blockIdx.y * BM;
    int n0 = blockIdx.x * BN;
    unsigned sbase = smem_u32(sm);

    const __nv_bfloat16* Bh = BhBase + (size_t)(m0 >> 11) * bStride;
    const __nv_bfloat16* Bl = BlBase + (size_t)(m0 >> 11) * bStride;

    int wid = tid >> 5, lane = tid & 31;
    int wm = (wid & 1) * 64;
    int wn = (wid >> 1) * 32;

    float acc[4][4][4];
#pragma unroll
    for (int i = 0; i < 4; i++)
#pragma unroll
        for (int j = 0; j < 4; j++)
#pragma unroll
            for (int v = 0; v < 4; v++) acc[i][j][v] = 0.f;

    load_stage(sbase, tid, 0, Ah, Al, Bh, Bl, m0, n0);
    CP_COMMIT();

    unsigned a_lo = (unsigned)((wm + (lane & 15)) * PK + ((lane >> 4) << 3)) * 2;
    unsigned b_lo = (unsigned)((wn + (lane & 15)) * PK + ((lane >> 4) << 3)) * 2;

    for (int it = 0; it < NIT; it++) {
        CP_WAIT(0);
        __syncthreads();
        if (it + 1 < NIT) {
            load_stage(sbase + (unsigned)((it + 1) & 1) * STAGEB, tid,
                       (it + 1) * BKE, Ah, Al, Bh, Bl, m0, n0);
            CP_COMMIT();
        }

        unsigned sbuf = sbase + (unsigned)(it & 1) * STAGEB;
#pragma unroll
        for (int kk = 0; kk < 2; kk++) {
            unsigned bh[2][4], bl[2][4];
            unsigned ao = sbuf + a_lo + (unsigned)kk * 32;
            unsigned bo = sbuf + b_lo + (unsigned)kk * 32;

#pragma unroll
            for (int L = 0; L < 2; L++) {
                LDSM4(bh[L][0], bh[L][1], bh[L][2], bh[L][3],
                      bo + TSZ * 4 + (unsigned)L * (16 * PK * 2));
                LDSM4(bl[L][0], bl[L][1], bl[L][2], bl[L][3],
                      bo + TSZ * 6 + (unsigned)L * (16 * PK * 2));
            }

#pragma unroll
            for (int ip = 0; ip < 4; ip += 2) {
                unsigned ah[2][4], al[2][4];
                LDSM4(ah[0][0], ah[0][1], ah[0][2], ah[0][3],
                      ao + (unsigned)ip * (16 * PK * 2));
                LDSM4(ah[1][0], ah[1][1], ah[1][2], ah[1][3],
                      ao + (unsigned)(ip + 1) * (16 * PK * 2));
#pragma unroll
                for (int u = 0; u < 2; u++)
#pragma unroll
                    for (int j = 0; j < 4; j++) {
                        int L = j >> 1, s = j & 1;
                        MMA(acc[ip + u][j], ah[u], bh[L][s], bh[L][s + 2]);
                    }
#pragma unroll
                for (int u = 0; u < 2; u++)
#pragma unroll
                    for (int j = 0; j < 4; j++) {
                        int L = j >> 1, s = j & 1;
                        MMA(acc[ip + u][j], ah[u], bl[L][s], bl[L][s + 2]);
                    }
                LDSM4(al[0][0], al[0][1], al[0][2], al[0][3],
                      ao + TSZ * 2 + (unsigned)ip * (16 * PK * 2));
                LDSM4(al[1][0], al[1][1], al[1][2], al[1][3],
                      ao + TSZ * 2 + (unsigned)(ip + 1) * (16 * PK * 2));
#pragma unroll
                for (int u = 0; u < 2; u++)
#pragma unroll
                    for (int j = 0; j < 4; j++) {
                        int L = j >> 1, s = j & 1;
                        MMA(acc[ip + u][j], al[u], bh[L][s], bh[L][s + 2]);
                    }
            }
        }
    }

    // epilogue
    int r = lane >> 2, c2 = (lane & 3) * 2;
#pragma unroll
    for (int i = 0; i < 4; i++) {
        int m = m0 + wm + i * 16 + r;
#pragma unroll
        for (int j = 0; j < 4; j++) {
            int n = n0 + wn + j * 8 + c2;
            float bv0 = (n < N) ? bias[n] : 0.f;
            float bv1 = (n + 1 < N) ? bias[n + 1] : 0.f;
            float v00 = acc[i][j][0] + bv0, v01 = acc[i][j][1] + bv1;
            float v10 = acc[i][j][2] + bv0, v11 = acc[i][j][3] + bv1;
            if (C) {
                float* C0 = C + (size_t)m * N;
                float* C1 = C0 + (size_t)8 * N;
                if (n < N)     { C0[n] = v00; C1[n] = v10; }
                if (n + 1 < N) { C0[n + 1] = v01; C1[n + 1] = v11; }
            }
            if (Sh) {
                unsigned* S0h = (unsigned*)(Sh + (size_t)m * EMBED);
                unsigned* S0l = (unsigned*)(Sl + (size_t)m * EMBED);
                unsigned* S1h = (unsigned*)(Sh + (size_t)(m + 8) * EMBED);
                unsigned* S1l = (unsigned*)(Sl + (size_t)(m + 8) * EMBED);
                unsigned h0 = pack_bf(v00, v01);
                unsigned h1 = pack_bf(v10, v11);
                float h0x = __uint_as_float(h0 << 16), h0y = __uint_as_float(h0 & 0xffff0000u);
                float h1x = __uint_as_float(h1 << 16), h1y = __uint_as_float(h1 & 0xffff0000u);
                S0h[n >> 1] = h0;
                S1h[n >> 1] = h1;
                S0l[n >> 1] = pack_bf(v00 - h0x, v01 - h0y);
                S1l[n >> 1] = pack_bf(v10 - h1x, v11 - h1y);
            }
        }
    }
}

// ---------- tensor-core Gram: Gpart[chunk][bh] = P_h^T P_h over 128 s-rows ----------
#define GPD 72   // padded row (bf16): 144B -> conflict-free trans ldmatrix

__global__ __launch_bounds__(256, 4) void head_gram_mma(
    const __nv_bfloat16* __restrict__ ph, const __nv_bfloat16* __restrict__ pl,
    float* __restrict__ Gpart)
{
    __shared__ __nv_bfloat16 sh[128][GPD];
    __shared__ __nv_bfloat16 sl[128][GPD];

    int bh = blockIdx.x;               // 0..31
    int chunk = blockIdx.y;            // 0..15
    int b = bh >> 4;
    int h = bh & 15;
    int tid = threadIdx.x;
    int wid = tid >> 5, lane = tid & 31;
    int wm = (wid & 1) * 32;           // d1 offset
    int wn = (wid >> 1) * 16;          // d2 offset

    unsigned shB = smem_u32(&sh[0][0]);
    unsigned slB = smem_u32(&sl[0][0]);

    int g = lane >> 3, l = lane & 7;
    unsigned aRowOff = (unsigned)(((g & 2) ? 8 : 0) + l) * (GPD * 2);
    unsigned aColOff = (unsigned)(wm + ((g & 1) ? 8 : 0)) * 2;
    unsigned bRowOff = (unsigned)(((g & 1) ? 8 : 0) + l) * (GPD * 2);
    unsigned bColOff = (unsigned)(wn + ((g >= 2) ? 8 : 0)) * 2;

    float acc[2][2][4];
#pragma unroll
    for (int i = 0; i < 2; i++)
#pragma unroll
        for (int j = 0; j < 2; j++)
#pragma unroll
            for (int v = 0; v < 4; v++) acc[i][j][v] = 0.f;

    int row = tid >> 1;                 // 0..127
    int q = tid & 1;                    // 32-elem half
    unsigned soff = (unsigned)(row * GPD + q * 32) * 2;

    // load one 128 x 64 tile of ph, pl
    size_t gbase = (size_t)(b * SEQ + chunk * 128 + row) * EMBED + h * HDIM + q * 32;
#pragma unroll
    for (int t = 0; t < 4; t++) {
        cpa16(shB + soff + t * 16, ph + gbase + t * 8);
        cpa16(slB + soff + t * 16, pl + gbase + t * 8);
    }
    CP_COMMIT();
    CP_WAIT(0);
    __syncthreads();

#pragma unroll
    for (int k0 = 0; k0 < 128; k0 += 16) {
        unsigned kb = (unsigned)k0 * (GPD * 2);
        unsigned Ah2[2][4], Al2[2][4], Bh4[4], Bl4[4];
#pragma unroll
        for (int i = 0; i < 2; i++) {
            LDSM4T(Ah2[i][0], Ah2[i][1], Ah2[i][2], Ah2[i][3],
                   shB + kb + aRowOff + aColOff + (unsigned)i * 32);
            LDSM4T(Al2[i][0], Al2[i][1], Al2[i][2], Al2[i][3],
                   slB + kb + aRowOff + aColOff + (unsigned)i * 32);
        }
        LDSM4T(Bh4[0], Bh4[1], Bh4[2], Bh4[3], shB + kb + bRowOff + bColOff);
        LDSM4T(Bl4[0], Bl4[1], Bl4[2], Bl4[3], slB + kb + bRowOff + bColOff);

#pragma unroll
        for (int i = 0; i < 2; i++)
#pragma unroll
            for (int j = 0; j < 2; j++) {
                MMA(acc[i][j], Ah2[i], Bh4[j * 2], Bh4[j * 2 + 1]);
                MMA(acc[i][j], Ah2[i], Bl4[j * 2], Bl4[j * 2 + 1]);
                MMA(acc[i][j], Al2[i], Bh4[j * 2], Bh4[j * 2 + 1]);
            }
    }

    float* Gp = Gpart + ((size_t)chunk * 32 + bh) * (HDIM * HDIM);
    int r = lane >> 2, c2 = (lane & 3) * 2;
#pragma unroll
    for (int i = 0; i < 2; i++) {
        int d1a = wm + i * 16 + r;
#pragma unroll
        for (int j = 0; j < 2; j++) {
            int d2 = wn + j * 8 + c2;
            Gp[d1a * HDIM + d2]           = acc[i][j][0];
            Gp[d1a * HDIM + d2 + 1]       = acc[i][j][1];
            Gp[(d1a + 8) * HDIM + d2]     = acc[i][j][2];
            Gp[(d1a + 8) * HDIM + d2 + 1] = acc[i][j][3];
        }
    }
}

__global__ void gram_reduce(const float* __restrict__ Gpart,
                            float* __restrict__ G, float scale)
{
    int idx = blockIdx.x * blockDim.x + threadIdx.x;
    if (idx >= 32 * HDIM * HDIM) return;
    float s = 0.f;
#pragma unroll
    for (int c = 0; c < GCHUNKS; c++)
        s += Gpart[(size_t)c * 32 * HDIM * HDIM + idx];
    G[idx] = s * scale;
}

// ---------- fused B2 build ----------
__global__ __launch_bounds__(256) void w2_build(
    const float* __restrict__ Wo, const float* __restrict__ G,
    __nv_bfloat16* __restrict__ B2h, __nv_bfloat16* __restrict__ B2l)
{
    int c0 = blockIdx.x * 64;
    int h  = blockIdx.y;
    int b  = blockIdx.z;
    const float* Gh = G + (size_t)(b * NHEADS + h) * HDIM * HDIM;

    __shared__ float Gs[64][65];
    __shared__ float Ws[64][65];
    int tid = threadIdx.x;

#pragma unroll
    for (int v = 0; v < 4; v++) {
        int idx = tid + v * 256;
        int rr = idx >> 4;
        int c = (idx & 15) << 2;
        float4 g4 = *(const float4*)(Gh + rr * HDIM + c);
        Gs[rr][c + 0] = g4.x; Gs[rr][c + 1] = g4.y;
        Gs[rr][c + 2] = g4.z; Gs[rr][c + 3] = g4.w;
        float4 w4 = make_float4(0.f, 0.f, 0.f, 0.f);
        if (c0 + rr < NCLS)
            w4 = *(const float4*)(Wo + (size_t)(c0 + rr) * EMBED + h * HDIM + c);
        Ws[rr][c + 0] = w4.x; Ws[rr][c + 1] = w4.y;
        Ws[rr][c + 2] = w4.z; Ws[rr][c + 3] = w4.w;
    }
    __syncthreads();

    int j  = tid & 63;
    int i0 = (tid >> 6) << 4;
    float acc[16];
#pragma unroll
    for (int ii = 0; ii < 16; ii++) acc[ii] = 0.f;

#pragma unroll 4
    for (int k = 0; k < 64; k++) {
        float g = Gs[k][j];
#pragma unroll
        for (int ii = 0; ii < 16; ii++)
            acc[ii] += Ws[i0 + ii][k] * g;
    }

#pragma unroll
    for (int ii = 0; ii < 16; ii++) {
        size_t o = (size_t)b * 1024 * EMBED + (size_t)(c0 + i0 + ii) * EMBED + h * HDIM + j;
        float v = acc[ii];
        __nv_bfloat16 hi = __float2bfloat16(v);
        B2h[o] = hi;
        B2l[o] = __float2bfloat16(v - __bfloat162float(hi));
    }
}

// ---------- launch ----------
extern "C" void kernel_launch(void* const* d_in, const int* in_sizes, int n_in,
                              void* d_out, int out_size)
{
    const float* x     = (const float*)d_in[0];
    const float* W_in  = (const float*)d_in[1];
    const float* b_in  = (const float*)d_in[2];
    const float* W_out = (const float*)d_in[3];
    const float* b_out = (const float*)d_in[4];
    float* out = (float*)d_out;

    int M = in_sizes[0] / EMBED;   // 4096

    float *G, *Gp;
    cudaGetSymbolAddress((void**)&G, g_G);
    cudaGetSymbolAddress((void**)&Gp, g_Gpart);
    __nv_bfloat16 *xh, *xl, *wih, *wil, *ph, *pl, *b2h, *b2l;
    cudaGetSymbolAddress((void**)&xh, g_xh);
    cudaGetSymbolAddress((void**)&xl, g_xl);
    cudaGetSymbolAddress((void**)&wih, g_wih);
    cudaGetSymbolAddress((void**)&wil, g_wil);
    cudaGetSymbolAddress((void**)&ph, g_ph);
    cudaGetSymbolAddress((void**)&pl, g_pl);
    cudaGetSymbolAddress((void**)&b2h, g_b2h);
    cudaGetSymbolAddress((void**)&b2l, g_b2l);

    cudaFuncSetAttribute(gemm_mma_bf16x3, cudaFuncAttributeMaxDynamicSharedMemorySize, SMEM_BYTES);

    dim3 blk(256);

    cvt_split<<<(M * EMBED / 4) / 256, blk>>>((const float4*)x, (uint2*)xh, (uint2*)xl, M * EMBED / 4);
    cvt_split<<<(EMBED * EMBED / 4) / 256, blk>>>((const float4*)W_in, (uint2*)wih, (uint2*)wil, EMBED * EMBED / 4);

    // 1) P = X @ W_in^T + b_in  -> hi/lo bf16 only
    gemm_mma_bf16x3<<<dim3(EMBED / BN, M / BM), blk, SMEM_BYTES>>>(
        xh, xl, wih, wil, b_in, nullptr, ph, pl, EMBED, 0);

    // 2) G = (1/32) * P_h^T P_h   (tensor cores; 16 chunks of 128 rows)
    head_gram_mma<<<dim3(32, GCHUNKS), blk>>>(ph, pl, Gp);
    gram_reduce<<<(32 * HDIM * HDIM + 255) / 256, blk>>>(Gp, G, 1.0f / 32.0f);

    // 3) B2[b] = blockdiag(G) @ W_out^T
    w2_build<<<dim3(1024 / 64, NHEADS, M / SEQ), blk>>>(W_out, G, b2h, b2l);

    // 4) out = P @ B2[b]^T + b_out
    gemm_mma_bf16x3<<<dim3(1024 / BN, M / BM), blk, SMEM_BYTES>>>(
        ph, pl, b2h, b2l, b_out, out, nullptr, nullptr, NCLS, (long)1024 * EMBED);
}

// round 12
// speedup vs baseline: 2.3751x; 1.3231x over previous
#include <cuda_runtime.h>
#include <cuda_fp16.h>
#include <cuda_bf16.h>

#define EMBED 1024
#define NHEADS 16
#define HDIM 64
#define SEQ 2048
#define NCLS 1000
#define GCHUNKS 16
#define MTOT 4096

#define BM 128
#define BN 128
#define BKE 32
#define NIT (EMBED / BKE)          // 32
#define PK 40                      // padded row (elems): 80B, ldmatrix conflict-free
#define TILEB (BM * PK * 2)        // 10240 B per tile
#define STAGEB (3 * TILEB)         // 30720 {A, Bh, Bl}
#define SMEM_BYTES (2 * STAGEB)    // 61440 -> 2 CTAs/SM

#define WSCALE 32.0f               // W_in pre-scale (keeps Wl out of fp16 subnormals)
#define B2SCALE 16.0f              // B2 pre-scale

// ---------- scratch ----------
__device__ float g_G[32 * HDIM * HDIM];
__device__ float g_Gpart[GCHUNKS][32][HDIM * HDIM];
__device__ __half g_xh[MTOT * EMBED];
__device__ __half g_wh[EMBED * EMBED], g_wl[EMBED * EMBED];
__device__ __half g_phh[MTOT * EMBED];                       // fp16 P (GEMM2 A)
__device__ __nv_bfloat16 g_pbh[MTOT * EMBED], g_pbl[MTOT * EMBED];  // bf16 split (gram)
__device__ __half g_b2h[2 * 1024 * EMBED], g_b2l[2 * 1024 * EMBED];

// ---------- helpers ----------
__device__ __forceinline__ unsigned smem_u32(const void* p) {
    unsigned a;
    asm("{ .reg .u64 t; cvta.to.shared.u64 t, %1; cvt.u32.u64 %0, t; }" : "=r"(a) : "l"(p));
    return a;
}
__device__ __forceinline__ void cpa16(unsigned s, const void* g) {
    asm volatile("cp.async.cg.shared.global [%0], [%1], 16;" :: "r"(s), "l"(g) : "memory");
}
#define CP_COMMIT() asm volatile("cp.async.commit_group;" ::: "memory")
#define CP_WAIT(n)  asm volatile("cp.async.wait_group %0;" :: "n"(n) : "memory")

#define LDSM4(r0, r1, r2, r3, a) \
    asm volatile("ldmatrix.sync.aligned.m8n8.x4.shared.b16 {%0,%1,%2,%3}, [%4];" \
        : "=r"(r0), "=r"(r1), "=r"(r2), "=r"(r3) : "r"(a))

#define LDSM4T(r0, r1, r2, r3, a) \
    asm volatile("ldmatrix.sync.aligned.m8n8.x4.trans.shared.b16 {%0,%1,%2,%3}, [%4];" \
        : "=r"(r0), "=r"(r1), "=r"(r2), "=r"(r3) : "r"(a))

#define MMABF(c, a, b0v, b1v) \
    asm volatile("mma.sync.aligned.m16n8k16.row.col.f32.bf16.bf16.f32 " \
        "{%0,%1,%2,%3},{%4,%5,%6,%7},{%8,%9},{%0,%1,%2,%3};" \
        : "+f"((c)[0]), "+f"((c)[1]), "+f"((c)[2]), "+f"((c)[3]) \
        : "r"((a)[0]), "r"((a)[1]), "r"((a)[2]), "r"((a)[3]), "r"(b0v), "r"(b1v))

#define MMAH(c, a, b0v, b1v) \
    asm volatile("mma.sync.aligned.m16n8k16.row.col.f32.f16.f16.f32 " \
        "{%0,%1,%2,%3},{%4,%5,%6,%7},{%8,%9},{%0,%1,%2,%3};" \
        : "+f"((c)[0]), "+f"((c)[1]), "+f"((c)[2]), "+f"((c)[3]) \
        : "r"((a)[0]), "r"((a)[1]), "r"((a)[2]), "r"((a)[3]), "r"(b0v), "r"(b1v))

__device__ __forceinline__ unsigned pack_bf(float e0, float e1) {
    unsigned r;
    asm("cvt.rn.bf16x2.f32 %0, %1, %2;" : "=r"(r) : "f"(e1), "f"(e0));
    return r;
}
__device__ __forceinline__ unsigned h2bits(__half2 h) {
    return *reinterpret_cast<unsigned*>(&h);
}

// ---------- cvt: x -> fp16 hi only ----------
__global__ void cvt_x_h(const float4* __restrict__ X, uint2* __restrict__ H, int n4) {
    int i = blockIdx.x * blockDim.x + threadIdx.x;
    if (i >= n4) return;
    float4 x = X[i];
    H[i] = make_uint2(h2bits(__floats2half2_rn(x.x, x.y)),
                      h2bits(__floats2half2_rn(x.z, x.w)));
}

// ---------- cvt: W -> (hi, lo) fp16, pre-scaled ----------
__global__ void cvt_w_split(const float4* __restrict__ X, uint2* __restrict__ H,
                            uint2* __restrict__ L, int n4, float scale) {
    int i = blockIdx.x * blockDim.x + threadIdx.x;
    if (i >= n4) return;
    float4 w = X[i];
    float sx = w.x * scale, sy = w.y * scale, sz = w.z * scale, sw = w.w * scale;
    __half hx = __float2half_rn(sx), hy = __float2half_rn(sy);
    __half hz = __float2half_rn(sz), hw = __float2half_rn(sw);
    H[i] = make_uint2(h2bits(__halves2half2(hx, hy)), h2bits(__halves2half2(hz, hw)));
    __half lx = __float2half_rn(sx - __half2float(hx));
    __half ly = __float2half_rn(sy - __half2float(hy));
    __half lz = __float2half_rn(sz - __half2float(hz));
    __half lw = __float2half_rn(sw - __half2float(hw));
    L[i] = make_uint2(h2bits(__halves2half2(lx, ly)), h2bits(__halves2half2(lz, lw)));
}

// ---------- fp16 two-term GEMM: C = (A @ (Bh+Bl)^T)*postScale + bias ----------
__device__ __forceinline__ void load_stage(
    unsigned sbuf, int tid, int k0,
    const __half* A, const __half* Bh, const __half* Bl, int m0, int n0)
{
    int row = tid >> 1;
    int hf = tid & 1;
    unsigned soff = (unsigned)(row * PK + hf * 16) * 2;
    size_t ga = (size_t)(m0 + row) * EMBED + k0 + hf * 16;
    size_t gb = (size_t)(n0 + row) * EMBED + k0 + hf * 16;
    cpa16(sbuf + soff,                     A + ga);
    cpa16(sbuf + soff + 16,                A + ga + 8);
    cpa16(sbuf + TILEB + soff,             Bh + gb);
    cpa16(sbuf + TILEB + soff + 16,        Bh + gb + 8);
    cpa16(sbuf + 2 * TILEB + soff,         Bl + gb);
    cpa16(sbuf + 2 * TILEB + soff + 16,    Bl + gb + 8);
}

__global__ __launch_bounds__(256, 2) void gemm_fp16x2(
    const __half* __restrict__ A,
    const __half* __restrict__ BhBase, const __half* __restrict__ BlBase,
    const float* __restrict__ bias, float postScale, float* __restrict__ C,
    __half* __restrict__ Ph, __nv_bfloat16* __restrict__ Sbh, __nv_bfloat16* __restrict__ Sbl,
    int N, long bStride)
{
    extern __shared__ char smc[];
    int tid = threadIdx.x;
    int m0 = blockIdx.y * BM;
    int n0 = blockIdx.x * BN;
    unsigned sbase = smem_u32(smc);

    const __half* Bh = BhBase + (size_t)(m0 >> 11) * bStride;
    const __half* Bl = BlBase + (size_t)(m0 >> 11) * bStride;

    int wid = tid >> 5, lane = tid & 31;
    int wm = (wid & 1) * 64;
    int wn = (wid >> 1) * 32;

    float acc[4][4][4];
#pragma unroll
    for (int i = 0; i < 4; i++)
#pragma unroll
        for (int j = 0; j < 4; j++)
#pragma unroll
            for (int v = 0; v < 4; v++) acc[i][j][v] = 0.f;

    load_stage(sbase, tid, 0, A, Bh, Bl, m0, n0);
    CP_COMMIT();

    unsigned a_lo = (unsigned)((wm + (lane & 15)) * PK + ((lane >> 4) << 3)) * 2;
    unsigned b_lo = (unsigned)((wn + (lane & 15)) * PK + ((lane >> 4) << 3)) * 2;

    for (int it = 0; it < NIT; it++) {
        CP_WAIT(0);
        __syncthreads();
        if (it + 1 < NIT) {
            load_stage(sbase + (unsigned)((it + 1) & 1) * STAGEB, tid,
                       (it + 1) * BKE, A, Bh, Bl, m0, n0);
            CP_COMMIT();
        }

        unsigned sbuf = sbase + (unsigned)(it & 1) * STAGEB;
#pragma unroll
        for (int kk = 0; kk < 2; kk++) {
            unsigned ah[4][4], bh[2][4], bl[2][4];
            unsigned ao = sbuf + a_lo + (unsigned)kk * 32;
            unsigned bo = sbuf + b_lo + (unsigned)kk * 32;

#pragma unroll
            for (int i = 0; i < 4; i++)
                LDSM4(ah[i][0], ah[i][1], ah[i][2], ah[i][3],
                      ao + (unsigned)i * (16 * PK * 2));
#pragma unroll
            for (int L = 0; L < 2; L++) {
                LDSM4(bh[L][0], bh[L][1], bh[L][2], bh[L][3],
                      bo + TILEB + (unsigned)L * (16 * PK * 2));
                LDSM4(bl[L][0], bl[L][1], bl[L][2], bl[L][3],
                      bo + 2 * TILEB + (unsigned)L * (16 * PK * 2));
            }
#pragma unroll
            for (int i = 0; i < 4; i++)
#pragma unroll
                for (int j = 0; j < 4; j++) {
                    int L = j >> 1, s = j & 1;
                    MMAH(acc[i][j], ah[i], bh[L][s], bh[L][s + 2]);
                }
#pragma unroll
            for (int i = 0; i < 4; i++)
#pragma unroll
                for (int j = 0; j < 4; j++) {
                    int L = j >> 1, s = j & 1;
                    MMAH(acc[i][j], ah[i], bl[L][s], bl[L][s + 2]);
                }
        }
    }

    // epilogue
    int r = lane >> 2, c2 = (lane & 3) * 2;
#pragma unroll
    for (int i = 0; i < 4; i++) {
        int m = m0 + wm + i * 16 + r;
#pragma unroll
        for (int j = 0; j < 4; j++) {
            int n = n0 + wn + j * 8 + c2;
            float bv0 = (n < N) ? bias[n] : 0.f;
            float bv1 = (n + 1 < N) ? bias[n + 1] : 0.f;
            float v00 = acc[i][j][0] * postScale + bv0;
            float v01 = acc[i][j][1] * postScale + bv1;
            float v10 = acc[i][j][2] * postScale + bv0;
            float v11 = acc[i][j][3] * postScale + bv1;
            if (C) {
                float* C0 = C + (size_t)m * N;
                float* C1 = C0 + (size_t)8 * N;
                if (n < N)     { C0[n] = v00; C1[n] = v10; }
                if (n + 1 < N) { C0[n + 1] = v01; C1[n + 1] = v11; }
            }
            if (Ph) {
#pragma unroll
                for (int rr = 0; rr < 2; rr++) {
                    int mm = m + rr * 8;
                    float e0 = rr ? v10 : v00, e1 = rr ? v11 : v01;
                    // fp16 P for GEMM2
                    *(unsigned*)((__half*)Ph + (size_t)mm * EMBED + n) =
                        h2bits(__floats2half2_rn(e0, e1));
                    // bf16 hi/lo split for gram
                    unsigned hp = pack_bf(e0, e1);
                    float hx = __uint_as_float(hp << 16);
                    float hy = __uint_as_float(hp & 0xffff0000u);
                    *(unsigned*)(Sbh + (size_t)mm * EMBED + n) = hp;
                    *(unsigned*)(Sbl + (size_t)mm * EMBED + n) = pack_bf(e0 - hx, e1 - hy);
                }
            }
        }
    }
}

// ---------- tensor-core Gram (bf16x3, from R11) ----------
#define GPD 72

__global__ __launch_bounds__(256, 4) void head_gram_mma(
    const __nv_bfloat16* __restrict__ ph, const __nv_bfloat16* __restrict__ pl,
    float* __restrict__ Gpart)
{
    __shared__ __nv_bfloat16 sh[128][GPD];
    __shared__ __nv_bfloat16 sl[128][GPD];

    int bh = blockIdx.x;
    int chunk = blockIdx.y;
    int b = bh >> 4;
    int h = bh & 15;
    int tid = threadIdx.x;
    int wid = tid >> 5, lane = tid & 31;
    int wm = (wid & 1) * 32;
    int wn = (wid >> 1) * 16;

    unsigned shB = smem_u32(&sh[0][0]);
    unsigned slB = smem_u32(&sl[0][0]);

    int g = lane >> 3, l = lane & 7;
    unsigned aRowOff = (unsigned)(((g & 2) ? 8 : 0) + l) * (GPD * 2);
    unsigned aColOff = (unsigned)(wm + ((g & 1) ? 8 : 0)) * 2;
    unsigned bRowOff = (unsigned)(((g & 1) ? 8 : 0) + l) * (GPD * 2);
    unsigned bColOff = (unsigned)(wn + ((g >= 2) ? 8 : 0)) * 2;

    float acc[2][2][4];
#pragma unroll
    for (int i = 0; i < 2; i++)
#pragma unroll
        for (int j = 0; j < 2; j++)
#pragma unroll
            for (int v = 0; v < 4; v++) acc[i][j][v] = 0.f;

    int row = tid >> 1;
    int q = tid & 1;
    unsigned soff = (unsigned)(row * GPD + q * 32) * 2;

    size_t gbase = (size_t)(b * SEQ + chunk * 128 + row) * EMBED + h * HDIM + q * 32;
#pragma unroll
    for (int t = 0; t < 4; t++) {
        cpa16(shB + soff + t * 16, ph + gbase + t * 8);
        cpa16(slB + soff + t * 16, pl + gbase + t * 8);
    }
    CP_COMMIT();
    CP_WAIT(0);
    __syncthreads();

#pragma unroll
    for (int k0 = 0; k0 < 128; k0 += 16) {
        unsigned kb = (unsigned)k0 * (GPD * 2);
        unsigned Ah2[2][4], Al2[2][4], Bh4[4], Bl4[4];
#pragma unroll
        for (int i = 0; i < 2; i++) {
            LDSM4T(Ah2[i][0], Ah2[i][1], Ah2[i][2], Ah2[i][3],
                   shB + kb + aRowOff + aColOff + (unsigned)i * 32);
            LDSM4T(Al2[i][0], Al2[i][1], Al2[i][2], Al2[i][3],
                   slB + kb + aRowOff + aColOff + (unsigned)i * 32);
        }
        LDSM4T(Bh4[0], Bh4[1], Bh4[2], Bh4[3], shB + kb + bRowOff + bColOff);
        LDSM4T(Bl4[0], Bl4[1], Bl4[2], Bl4[3], slB + kb + bRowOff + bColOff);

#pragma unroll
        for (int i = 0; i < 2; i++)
#pragma unroll
            for (int j = 0; j < 2; j++) {
                MMABF(acc[i][j], Ah2[i], Bh4[j * 2], Bh4[j * 2 + 1]);
                MMABF(acc[i][j], Ah2[i], Bl4[j * 2], Bl4[j * 2 + 1]);
                MMABF(acc[i][j], Al2[i], Bh4[j * 2], Bh4[j * 2 + 1]);
            }
    }

    float* Gp = Gpart + ((size_t)chunk * 32 + bh) * (HDIM * HDIM);
    int r = lane >> 2, c2 = (lane & 3) * 2;
#pragma unroll
    for (int i = 0; i < 2; i++) {
        int d1a = wm + i * 16 + r;
#pragma unroll
        for (int j = 0; j < 2; j++) {
            int d2 = wn + j * 8 + c2;
            Gp[d1a * HDIM + d2]           = acc[i][j][0];
            Gp[d1a * HDIM + d2 + 1]       = acc[i][j][1];
            Gp[(d1a + 8) * HDIM + d2]     = acc[i][j][2];
            Gp[(d1a + 8) * HDIM + d2 + 1] = acc[i][j][3];
        }
    }
}

__global__ void gram_reduce(const float* __restrict__ Gpart,
                            float* __restrict__ G, float scale)
{
    int idx = blockIdx.x * blockDim.x + threadIdx.x;
    if (idx >= 32 * HDIM * HDIM) return;
    float s = 0.f;
#pragma unroll
    for (int c = 0; c < GCHUNKS; c++)
        s += Gpart[(size_t)c * 32 * HDIM * HDIM + idx];
    G[idx] = s * scale;
}

// ---------- fused B2 build: fp16 hi/lo, pre-scaled ----------
__global__ __launch_bounds__(256) void w2_build(
    const float* __restrict__ Wo, const float* __restrict__ G,
    __half* __restrict__ B2h, __half* __restrict__ B2l)
{
    int c0 = blockIdx.x * 64;
    int h  = blockIdx.y;
    int b  = blockIdx.z;
    const float* Gh = G + (size_t)(b * NHEADS + h) * HDIM * HDIM;

    __shared__ float Gs[64][65];
    __shared__ float Ws[64][65];
    int tid = threadIdx.x;

#pragma unroll
    for (int v = 0; v < 4; v++) {
        int idx = tid + v * 256;
        int rr = idx >> 4;
        int c = (idx & 15) << 2;
        float4 g4 = *(const float4*)(Gh + rr * HDIM + c);
        Gs[rr][c + 0] = g4.x; Gs[rr][c + 1] = g4.y;
        Gs[rr][c + 2] = g4.z; Gs[rr][c + 3] = g4.w;
        float4 w4 = make_float4(0.f, 0.f, 0.f, 0.f);
        if (c0 + rr < NCLS)
            w4 = *(const float4*)(Wo + (size_t)(c0 + rr) * EMBED + h * HDIM + c);
        Ws[rr][c + 0] = w4.x; Ws[rr][c + 1] = w4.y;
        Ws[rr][c + 2] = w4.z; Ws[rr][c + 3] = w4.w;
    }
    __syncthreads();

    int j  = tid & 63;
    int i0 = (tid >> 6) << 4;
    float acc[16];
#pragma unroll
    for (int ii = 0; ii < 16; ii++) acc[ii] = 0.f;

#pragma unroll 4
    for (int k = 0; k < 64; k++) {
        float g = Gs[k][j];
#pragma unroll
        for (int ii = 0; ii < 16; ii++)
            acc[ii] += Ws[i0 + ii][k] * g;
    }

#pragma unroll
    for (int ii = 0; ii < 16; ii++) {
        size_t o = (size_t)b * 1024 * EMBED + (size_t)(c0 + i0 + ii) * EMBED + h * HDIM + j;
        float vs = acc[ii] * B2SCALE;
        __half hi = __float2half_rn(vs);
        B2h[o] = hi;
        B2l[o] = __float2half_rn(vs - __half2float(hi));
    }
}

// ---------- launch ----------
extern "C" void kernel_launch(void* const* d_in, const int* in_sizes, int n_in,
                              void* d_out, int out_size)
{
    const float* x     = (const float*)d_in[0];
    const float* W_in  = (const float*)d_in[1];
    const float* b_in  = (const float*)d_in[2];
    const float* W_out = (const float*)d_in[3];
    const float* b_out = (const float*)d_in[4];
    float* out = (float*)d_out;

    int M = in_sizes[0] / EMBED;   // 4096

    float *G, *Gp;
    cudaGetSymbolAddress((void**)&G, g_G);
    cudaGetSymbolAddress((void**)&Gp, g_Gpart);
    __half *xh, *wh, *wl, *phh, *b2h, *b2l;
    cudaGetSymbolAddress((void**)&xh, g_xh);
    cudaGetSymbolAddress((void**)&wh, g_wh);
    cudaGetSymbolAddress((void**)&wl, g_wl);
    cudaGetSymbolAddress((void**)&phh, g_phh);
    cudaGetSymbolAddress((void**)&b2h, g_b2h);
    cudaGetSymbolAddress((void**)&b2l, g_b2l);
    __nv_bfloat16 *pbh, *pbl;
    cudaGetSymbolAddress((void**)&pbh, g_pbh);
    cudaGetSymbolAddress((void**)&pbl, g_pbl);

    cudaFuncSetAttribute(gemm_fp16x2, cudaFuncAttributeMaxDynamicSharedMemorySize, SMEM_BYTES);

    dim3 blk(256);

    // quantize: x -> fp16 hi; W_in*32 -> fp16 hi/lo
    cvt_x_h<<<(M * EMBED / 4) / 256, blk>>>((const float4*)x, (uint2*)xh, M * EMBED / 4);
    cvt_w_split<<<(EMBED * EMBED / 4) / 256, blk>>>((const float4*)W_in, (uint2*)wh, (uint2*)wl,
                                                    EMBED * EMBED / 4, WSCALE);

    // 1) P = X @ W_in^T + b_in  (fp16 2-term; epilogue -> fp16 P + bf16 hi/lo)
    gemm_fp16x2<<<dim3(EMBED / BN, M / BM), blk, SMEM_BYTES>>>(
        xh, wh, wl, b_in, 1.0f / WSCALE, nullptr, phh, pbh, pbl, EMBED, 0);

    // 2) G = (1/32) * P_h^T P_h  (bf16x3 tensor cores)
    head_gram_mma<<<dim3(32, GCHUNKS), blk>>>(pbh, pbl, Gp);
    gram_reduce<<<(32 * HDIM * HDIM + 255) / 256, blk>>>(Gp, G, 1.0f / 32.0f);

    // 3) B2[b] = blockdiag(G) @ W_out^T  (fp16 hi/lo, x16)
    w2_build<<<dim3(1024 / 64, NHEADS, M / SEQ), blk>>>(W_out, G, b2h, b2l);

    // 4) out = P @ B2[b]^T + b_out  (fp16 2-term)
    gemm_fp16x2<<<dim3(1024 / BN, M / BM), blk, SMEM_BYTES>>>(
        phh, b2h, b2l, b_out, 1.0f / B2SCALE, out, nullptr, nullptr, nullptr,
        NCLS, (long)1024 * EMBED);
}

// round 13
// speedup vs baseline: 3.5046x; 1.4756x over previous
#include <cuda_runtime.h>
#include <cuda_fp16.h>
#include <cuda_bf16.h>

#define EMBED 1024
#define NHEADS 16
#define HDIM 64
#define SEQ 2048
#define NCLS 1000
#define GCHUNKS 16
#define MTOT 4096

#define BM 128
#define BN 128
#define BKE 32
#define NIT (EMBED / BKE)          // 32
#define PK 40                      // padded row (elems): 80B, ldmatrix conflict-free
#define TILEB (BM * PK * 2)        // 10240 B per tile
#define STAGEB (2 * TILEB)         // 20480 {A, B}
#define SMEM_BYTES (2 * STAGEB)    // 40960

#define WSCALE 32.0f               // W_in pre-scale
#define B2SCALE 16.0f              // B2 pre-scale

// ---------- scratch ----------
__device__ float g_G[32 * HDIM * HDIM];
__device__ float g_Gpart[GCHUNKS][32][HDIM * HDIM];
__device__ __half g_xh[MTOT * EMBED];
__device__ __half g_wh[EMBED * EMBED];
__device__ __half g_phh[MTOT * EMBED];                              // fp16 P (GEMM2 A)
__device__ __nv_bfloat16 g_pbh[MTOT * EMBED], g_pbl[MTOT * EMBED];  // bf16 split (gram)
__device__ __half g_b2h[2 * 1024 * EMBED];

// ---------- helpers ----------
__device__ __forceinline__ unsigned smem_u32(const void* p) {
    unsigned a;
    asm("{ .reg .u64 t; cvta.to.shared.u64 t, %1; cvt.u32.u64 %0, t; }" : "=r"(a) : "l"(p));
    return a;
}
__device__ __forceinline__ void cpa16(unsigned s, const void* g) {
    asm volatile("cp.async.cg.shared.global [%0], [%1], 16;" :: "r"(s), "l"(g) : "memory");
}
#define CP_COMMIT() asm volatile("cp.async.commit_group;" ::: "memory")
#define CP_WAIT(n)  asm volatile("cp.async.wait_group %0;" :: "n"(n) : "memory")

#define LDSM4(r0, r1, r2, r3, a) \
    asm volatile("ldmatrix.sync.aligned.m8n8.x4.shared.b16 {%0,%1,%2,%3}, [%4];" \
        : "=r"(r0), "=r"(r1), "=r"(r2), "=r"(r3) : "r"(a))

#define LDSM4T(r0, r1, r2, r3, a) \
    asm volatile("ldmatrix.sync.aligned.m8n8.x4.trans.shared.b16 {%0,%1,%2,%3}, [%4];" \
        : "=r"(r0), "=r"(r1), "=r"(r2), "=r"(r3) : "r"(a))

#define MMABF(c, a, b0v, b1v) \
    asm volatile("mma.sync.aligned.m16n8k16.row.col.f32.bf16.bf16.f32 " \
        "{%0,%1,%2,%3},{%4,%5,%6,%7},{%8,%9},{%0,%1,%2,%3};" \
        : "+f"((c)[0]), "+f"((c)[1]), "+f"((c)[2]), "+f"((c)[3]) \
        : "r"((a)[0]), "r"((a)[1]), "r"((a)[2]), "r"((a)[3]), "r"(b0v), "r"(b1v))

#define MMAH(c, a, b0v, b1v) \
    asm volatile("mma.sync.aligned.m16n8k16.row.col.f32.f16.f16.f32 " \
        "{%0,%1,%2,%3},{%4,%5,%6,%7},{%8,%9},{%0,%1,%2,%3};" \
        : "+f"((c)[0]), "+f"((c)[1]), "+f"((c)[2]), "+f"((c)[3]) \
        : "r"((a)[0]), "r"((a)[1]), "r"((a)[2]), "r"((a)[3]), "r"(b0v), "r"(b1v))

__device__ __forceinline__ unsigned pack_bf(float e0, float e1) {
    unsigned r;
    asm("cvt.rn.bf16x2.f32 %0, %1, %2;" : "=r"(r) : "f"(e1), "f"(e0));
    return r;
}
__device__ __forceinline__ unsigned h2bits(__half2 h) {
    return *reinterpret_cast<unsigned*>(&h);
}

// ---------- cvt: fp32 -> fp16 (optional pre-scale) ----------
__global__ void cvt_h(const float4* __restrict__ X, uint2* __restrict__ H, int n4, float scale) {
    int i = blockIdx.x * blockDim.x + threadIdx.x;
    if (i >= n4) return;
    float4 x = X[i];
    H[i] = make_uint2(h2bits(__floats2half2_rn(x.x * scale, x.y * scale)),
                      h2bits(__floats2half2_rn(x.z * scale, x.w * scale)));
}

// ---------- fp16 single-term GEMM: C = (A @ B^T)*postScale + bias ----------
__device__ __forceinline__ void load_stage(
    unsigned sbuf, int tid, int k0,
    const __half* A, const __half* B, int m0, int n0)
{
    int row = tid >> 1;
    int hf = tid & 1;
    unsigned soff = (unsigned)(row * PK + hf * 16) * 2;
    size_t ga = (size_t)(m0 + row) * EMBED + k0 + hf * 16;
    size_t gb = (size_t)(n0 + row) * EMBED + k0 + hf * 16;
    cpa16(sbuf + soff,              A + ga);
    cpa16(sbuf + soff + 16,         A + ga + 8);
    cpa16(sbuf + TILEB + soff,      B + gb);
    cpa16(sbuf + TILEB + soff + 16, B + gb + 8);
}

__global__ __launch_bounds__(256, 2) void gemm_fp16(
    const __half* __restrict__ A, const __half* __restrict__ BBase,
    const float* __restrict__ bias, float postScale, float* __restrict__ C,
    __half* __restrict__ Ph, __nv_bfloat16* __restrict__ Sbh, __nv_bfloat16* __restrict__ Sbl,
    int N, long bStride)
{
    extern __shared__ char smc[];
    int tid = threadIdx.x;
    int m0 = blockIdx.y * BM;
    int n0 = blockIdx.x * BN;
    unsigned sbase = smem_u32(smc);

    const __half* B = BBase + (size_t)(m0 >> 11) * bStride;

    int wid = tid >> 5, lane = tid & 31;
    int wm = (wid & 1) * 64;
    int wn = (wid >> 1) * 32;

    float acc[4][4][4];
#pragma unroll
    for (int i = 0; i < 4; i++)
#pragma unroll
        for (int j = 0; j < 4; j++)
#pragma unroll
            for (int v = 0; v < 4; v++) acc[i][j][v] = 0.f;

    load_stage(sbase, tid, 0, A, B, m0, n0);
    CP_COMMIT();

    unsigned a_lo = (unsigned)((wm + (lane & 15)) * PK + ((lane >> 4) << 3)) * 2;
    unsigned b_lo = (unsigned)((wn + (lane & 15)) * PK + ((lane >> 4) << 3)) * 2;

    for (int it = 0; it < NIT; it++) {
        CP_WAIT(0);
        __syncthreads();
        if (it + 1 < NIT) {
            load_stage(sbase + (unsigned)((it + 1) & 1) * STAGEB, tid,
                       (it + 1) * BKE, A, B, m0, n0);
            CP_COMMIT();
        }

        unsigned sbuf = sbase + (unsigned)(it & 1) * STAGEB;
#pragma unroll
        for (int kk = 0; kk < 2; kk++) {
            unsigned ah[4][4], bb[2][4];
            unsigned ao = sbuf + a_lo + (unsigned)kk * 32;
            unsigned bo = sbuf + b_lo + (unsigned)kk * 32;

#pragma unroll
            for (int i = 0; i < 4; i++)
                LDSM4(ah[i][0], ah[i][1], ah[i][2], ah[i][3],
                      ao + (unsigned)i * (16 * PK * 2));
#pragma unroll
            for (int L = 0; L < 2; L++)
                LDSM4(bb[L][0], bb[L][1], bb[L][2], bb[L][3],
                      bo + TILEB + (unsigned)L * (16 * PK * 2));
#pragma unroll
            for (int i = 0; i < 4; i++)
#pragma unroll
                for (int j = 0; j < 4; j++) {
                    int L = j >> 1, s = j & 1;
                    MMAH(acc[i][j], ah[i], bb[L][s], bb[L][s + 2]);
                }
        }
    }

    // epilogue
    int r = lane >> 2, c2 = (lane & 3) * 2;
#pragma unroll
    for (int i = 0; i < 4; i++) {
        int m = m0 + wm + i * 16 + r;
#pragma unroll
        for (int j = 0; j < 4; j++) {
            int n = n0 + wn + j * 8 + c2;
            float bv0 = (n < N) ? bias[n] : 0.f;
            float bv1 = (n + 1 < N) ? bias[n + 1] : 0.f;
            float v00 = acc[i][j][0] * postScale + bv0;
            float v01 = acc[i][j][1] * postScale + bv1;
            float v10 = acc[i][j][2] * postScale + bv0;
            float v11 = acc[i][j][3] * postScale + bv1;
            if (C) {
                float* C0 = C + (size_t)m * N;
                float* C1 = C0 + (size_t)8 * N;
                if (n < N)     { C0[n] = v00; C1[n] = v10; }
                if (n + 1 < N) { C0[n + 1] = v01; C1[n + 1] = v11; }
            }
            if (Ph) {
#pragma unroll
                for (int rr = 0; rr < 2; rr++) {
                    int mm = m + rr * 8;
                    float e0 = rr ? v10 : v00, e1 = rr ? v11 : v01;
                    *(unsigned*)((__half*)Ph + (size_t)mm * EMBED + n) =
                        h2bits(__floats2half2_rn(e0, e1));
                    unsigned hp = pack_bf(e0, e1);
                    float hx = __uint_as_float(hp << 16);
                    float hy = __uint_as_float(hp & 0xffff0000u);
                    *(unsigned*)(Sbh + (size_t)mm * EMBED + n) = hp;
                    *(unsigned*)(Sbl + (size_t)mm * EMBED + n) = pack_bf(e0 - hx, e1 - hy);
                }
            }
        }
    }
}

// ---------- tensor-core Gram (bf16x3, unchanged) ----------
#define GPD 72

__global__ __launch_bounds__(256, 4) void head_gram_mma(
    const __nv_bfloat16* __restrict__ ph, const __nv_bfloat16* __restrict__ pl,
    float* __restrict__ Gpart)
{
    __shared__ __nv_bfloat16 sh[128][GPD];
    __shared__ __nv_bfloat16 sl[128][GPD];

    int bh = blockIdx.x;
    int chunk = blockIdx.y;
    int b = bh >> 4;
    int h = bh & 15;
    int tid = threadIdx.x;
    int wid = tid >> 5, lane = tid & 31;
    int wm = (wid & 1) * 32;
    int wn = (wid >> 1) * 16;

    unsigned shB = smem_u32(&sh[0][0]);
    unsigned slB = smem_u32(&sl[0][0]);

    int g = lane >> 3, l = lane & 7;
    unsigned aRowOff = (unsigned)(((g & 2) ? 8 : 0) + l) * (GPD * 2);
    unsigned aColOff = (unsigned)(wm + ((g & 1) ? 8 : 0)) * 2;
    unsigned bRowOff = (unsigned)(((g & 1) ? 8 : 0) + l) * (GPD * 2);
    unsigned bColOff = (unsigned)(wn + ((g >= 2) ? 8 : 0)) * 2;

    float acc[2][2][4];
#pragma unroll
    for (int i = 0; i < 2; i++)
#pragma unroll
        for (int j = 0; j < 2; j++)
#pragma unroll
            for (int v = 0; v < 4; v++) acc[i][j][v] = 0.f;

    int row = tid >> 1;
    int q = tid & 1;
    unsigned soff = (unsigned)(row * GPD + q * 32) * 2;

    size_t gbase = (size_t)(b * SEQ + chunk * 128 + row) * EMBED + h * HDIM + q * 32;
#pragma unroll
    for (int t = 0; t < 4; t++) {
        cpa16(shB + soff + t * 16, ph + gbase + t * 8);
        cpa16(slB + soff + t * 16, pl + gbase + t * 8);
    }
    CP_COMMIT();
    CP_WAIT(0);
    __syncthreads();

#pragma unroll
    for (int k0 = 0; k0 < 128; k0 += 16) {
        unsigned kb = (unsigned)k0 * (GPD * 2);
        unsigned Ah2[2][4], Al2[2][4], Bh4[4], Bl4[4];
#pragma unroll
        for (int i = 0; i < 2; i++) {
            LDSM4T(Ah2[i][0], Ah2[i][1], Ah2[i][2], Ah2[i][3],
                   shB + kb + aRowOff + aColOff + (unsigned)i * 32);
            LDSM4T(Al2[i][0], Al2[i][1], Al2[i][2], Al2[i][3],
                   slB + kb + aRowOff + aColOff + (unsigned)i * 32);
        }
        LDSM4T(Bh4[0], Bh4[1], Bh4[2], Bh4[3], shB + kb + bRowOff + bColOff);
        LDSM4T(Bl4[0], Bl4[1], Bl4[2], Bl4[3], slB + kb + bRowOff + bColOff);

#pragma unroll
        for (int i = 0; i < 2; i++)
#pragma unroll
            for (int j = 0; j < 2; j++) {
                MMABF(acc[i][j], Ah2[i], Bh4[j * 2], Bh4[j * 2 + 1]);
                MMABF(acc[i][j], Ah2[i], Bl4[j * 2], Bl4[j * 2 + 1]);
                MMABF(acc[i][j], Al2[i], Bh4[j * 2], Bh4[j * 2 + 1]);
            }
    }

    float* Gp = Gpart + ((size_t)chunk * 32 + bh) * (HDIM * HDIM);
    int r = lane >> 2, c2 = (lane & 3) * 2;
#pragma unroll
    for (int i = 0; i < 2; i++) {
        int d1a = wm + i * 16 + r;
#pragma unroll
        for (int j = 0; j < 2; j++) {
            int d2 = wn + j * 8 + c2;
            Gp[d1a * HDIM + d2]           = acc[i][j][0];
            Gp[d1a * HDIM + d2 + 1]       = acc[i][j][1];
            Gp[(d1a + 8) * HDIM + d2]     = acc[i][j][2];
            Gp[(d1a + 8) * HDIM + d2 + 1] = acc[i][j][3];
        }
    }
}

__global__ void gram_reduce(const float* __restrict__ Gpart,
                            float* __restrict__ G, float scale)
{
    int idx = blockIdx.x * blockDim.x + threadIdx.x;
    if (idx >= 32 * HDIM * HDIM) return;
    float s = 0.f;
#pragma unroll
    for (int c = 0; c < GCHUNKS; c++)
        s += Gpart[(size_t)c * 32 * HDIM * HDIM + idx];
    G[idx] = s * scale;
}

// ---------- fused B2 build: fp16 hi only, pre-scaled ----------
__global__ __launch_bounds__(256) void w2_build(
    const float* __restrict__ Wo, const float* __restrict__ G,
    __half* __restrict__ B2h)
{
    int c0 = blockIdx.x * 64;
    int h  = blockIdx.y;
    int b  = blockIdx.z;
    const float* Gh = G + (size_t)(b * NHEADS + h) * HDIM * HDIM;

    __shared__ float Gs[64][65];
    __shared__ float Ws[64][65];
    int tid = threadIdx.x;

#pragma unroll
    for (int v = 0; v < 4; v++) {
        int idx = tid + v * 256;
        int rr = idx >> 4;
        int c = (idx & 15) << 2;
        float4 g4 = *(const float4*)(Gh + rr * HDIM + c);
        Gs[rr][c + 0] = g4.x; Gs[rr][c + 1] = g4.y;
        Gs[rr][c + 2] = g4.z; Gs[rr][c + 3] = g4.w;
        float4 w4 = make_float4(0.f, 0.f, 0.f, 0.f);
        if (c0 + rr < NCLS)
            w4 = *(const float4*)(Wo + (size_t)(c0 + rr) * EMBED + h * HDIM + c);
        Ws[rr][c + 0] = w4.x; Ws[rr][c + 1] = w4.y;
        Ws[rr][c + 2] = w4.z; Ws[rr][c + 3] = w4.w;
    }
    __syncthreads();

    int j  = tid & 63;
    int i0 = (tid >> 6) << 4;
    float acc[16];
#pragma unroll
    for (int ii = 0; ii < 16; ii++) acc[ii] = 0.f;

#pragma unroll 4
    for (int k = 0; k < 64; k++) {
        float g = Gs[k][j];
#pragma unroll
        for (int ii = 0; ii < 16; ii++)
            acc[ii] += Ws[i0 + ii][k] * g;
    }

#pragma unroll
    for (int ii = 0; ii < 16; ii++) {
        size_t o = (size_t)b * 1024 * EMBED + (size_t)(c0 + i0 + ii) * EMBED + h * HDIM + j;
        B2h[o] = __float2half_rn(acc[ii] * B2SCALE);
    }
}

// ---------- launch ----------
extern "C" void kernel_launch(void* const* d_in, const int* in_sizes, int n_in,
                              void* d_out, int out_size)
{
    const float* x     = (const float*)d_in[0];
    const float* W_in  = (const float*)d_in[1];
    const float* b_in  = (const float*)d_in[2];
    const float* W_out = (const float*)d_in[3];
    const float* b_out = (const float*)d_in[4];
    float* out = (float*)d_out;

    int M = in_sizes[0] / EMBED;   // 4096

    float *G, *Gp;
    cudaGetSymbolAddress((void**)&G, g_G);
    cudaGetSymbolAddress((void**)&Gp, g_Gpart);
    __half *xh, *wh, *phh, *b2h;
    cudaGetSymbolAddress((void**)&xh, g_xh);
    cudaGetSymbolAddress((void**)&wh, g_wh);
    cudaGetSymbolAddress((void**)&phh, g_phh);
    cudaGetSymbolAddress((void**)&b2h, g_b2h);
    __nv_bfloat16 *pbh, *pbl;
    cudaGetSymbolAddress((void**)&pbh, g_pbh);
    cudaGetSymbolAddress((void**)&pbl, g_pbl);

    cudaFuncSetAttribute(gemm_fp16, cudaFuncAttributeMaxDynamicSharedMemorySize, SMEM_BYTES);

    dim3 blk(256);

    // quantize: x -> fp16; W_in*32 -> fp16
    cvt_h<<<(M * EMBED / 4) / 256, blk>>>((const float4*)x, (uint2*)xh, M * EMBED / 4, 1.0f);
    cvt_h<<<(EMBED * EMBED / 4) / 256, blk>>>((const float4*)W_in, (uint2*)wh,
                                              EMBED * EMBED / 4, WSCALE);

    // 1) P = X @ W_in^T + b_in  (fp16; epilogue -> fp16 P + bf16 hi/lo for gram)
    gemm_fp16<<<dim3(EMBED / BN, M / BM), blk, SMEM_BYTES>>>(
        xh, wh, b_in, 1.0f / WSCALE, nullptr, phh, pbh, pbl, EMBED, 0);

    // 2) G = (1/32) * P_h^T P_h  (bf16x3 tensor cores — keeps G near-exact)
    head_gram_mma<<<dim3(32, GCHUNKS), blk>>>(pbh, pbl, Gp);
    gram_reduce<<<(32 * HDIM * HDIM + 255) / 256, blk>>>(Gp, G, 1.0f / 32.0f);

    // 3) B2[b] = blockdiag(G) @ W_out^T  (fp16, x16)
    w2_build<<<dim3(1024 / 64, NHEADS, M / SEQ), blk>>>(W_out, G, b2h);

    // 4) out = P @ B2[b]^T + b_out  (fp16)
    gemm_fp16<<<dim3(1024 / BN, M / BM), blk, SMEM_BYTES>>>(
        phh, b2h, b_out, 1.0f / B2SCALE, out, nullptr, nullptr, nullptr,
        NCLS, (long)1024 * EMBED);
}

// round 14
// speedup vs baseline: 3.7913x; 1.0818x over previous
#include <cuda_runtime.h>
#include <cuda_fp16.h>

#define EMBED 1024
#define NHEADS 16
#define HDIM 64
#define SEQ 2048
#define NCLS 1000
#define GCHUNKS 16
#define MTOT 4096

#define BM 128
#define BN 128
#define BKE 32
#define NIT (EMBED / BKE)          // 32
#define PK 40                      // padded row (elems): 80B, ldmatrix conflict-free
#define TILEB (BM * PK * 2)        // 10240 B per tile
#define STAGEB (2 * TILEB)         // 20480 {A, B}
#define SMEM_BYTES (2 * STAGEB)    // 40960

#define WSCALE 32.0f               // W_in pre-scale
#define B2SCALE 16.0f              // B2 pre-scale

// ---------- scratch ----------
__device__ float g_G[32 * HDIM * HDIM];
__device__ float g_Gpart[GCHUNKS][32][HDIM * HDIM];
__device__ __half g_xh[MTOT * EMBED];
__device__ __half g_wh[EMBED * EMBED];
__device__ __half g_phh[MTOT * EMBED];        // fp16 P (GEMM2 A + gram source)
__device__ __half g_b2h[2 * 1024 * EMBED];

// ---------- helpers ----------
__device__ __forceinline__ unsigned smem_u32(const void* p) {
    unsigned a;
    asm("{ .reg .u64 t; cvta.to.shared.u64 t, %1; cvt.u32.u64 %0, t; }" : "=r"(a) : "l"(p));
    return a;
}
__device__ __forceinline__ void cpa16(unsigned s, const void* g) {
    asm volatile("cp.async.cg.shared.global [%0], [%1], 16;" :: "r"(s), "l"(g) : "memory");
}
#define CP_COMMIT() asm volatile("cp.async.commit_group;" ::: "memory")
#define CP_WAIT(n)  asm volatile("cp.async.wait_group %0;" :: "n"(n) : "memory")

#define LDSM4(r0, r1, r2, r3, a) \
    asm volatile("ldmatrix.sync.aligned.m8n8.x4.shared.b16 {%0,%1,%2,%3}, [%4];" \
        : "=r"(r0), "=r"(r1), "=r"(r2), "=r"(r3) : "r"(a))

#define LDSM4T(r0, r1, r2, r3, a) \
    asm volatile("ldmatrix.sync.aligned.m8n8.x4.trans.shared.b16 {%0,%1,%2,%3}, [%4];" \
        : "=r"(r0), "=r"(r1), "=r"(r2), "=r"(r3) : "r"(a))

#define MMAH(c, a, b0v, b1v) \
    asm volatile("mma.sync.aligned.m16n8k16.row.col.f32.f16.f16.f32 " \
        "{%0,%1,%2,%3},{%4,%5,%6,%7},{%8,%9},{%0,%1,%2,%3};" \
        : "+f"((c)[0]), "+f"((c)[1]), "+f"((c)[2]), "+f"((c)[3]) \
        : "r"((a)[0]), "r"((a)[1]), "r"((a)[2]), "r"((a)[3]), "r"(b0v), "r"(b1v))

__device__ __forceinline__ unsigned h2bits(__half2 h) {
    return *reinterpret_cast<unsigned*>(&h);
}

// ---------- cvt: fp32 -> fp16 (optional pre-scale) ----------
__global__ void cvt_h(const float4* __restrict__ X, uint2* __restrict__ H, int n4, float scale) {
    int i = blockIdx.x * blockDim.x + threadIdx.x;
    if (i >= n4) return;
    float4 x = X[i];
    H[i] = make_uint2(h2bits(__floats2half2_rn(x.x * scale, x.y * scale)),
                      h2bits(__floats2half2_rn(x.z * scale, x.w * scale)));
}

// ---------- fp16 single-term GEMM: C = (A @ B^T)*postScale + bias ----------
__device__ __forceinline__ void load_stage(
    unsigned sbuf, int tid, int k0,
    const __half* A, const __half* B, int m0, int n0)
{
    int row = tid >> 1;
    int hf = tid & 1;
    unsigned soff = (unsigned)(row * PK + hf * 16) * 2;
    size_t ga = (size_t)(m0 + row) * EMBED + k0 + hf * 16;
    size_t gb = (size_t)(n0 + row) * EMBED + k0 + hf * 16;
    cpa16(sbuf + soff,              A + ga);
    cpa16(sbuf + soff + 16,         A + ga + 8);
    cpa16(sbuf + TILEB + soff,      B + gb);
    cpa16(sbuf + TILEB + soff + 16, B + gb + 8);
}

__global__ __launch_bounds__(256, 2) void gemm_fp16(
    const __half* __restrict__ A, const __half* __restrict__ BBase,
    const float* __restrict__ bias, float postScale, float* __restrict__ C,
    __half* __restrict__ Ph, int N, long bStride)
{
    extern __shared__ char smc[];
    int tid = threadIdx.x;
    int m0 = blockIdx.y * BM;
    int n0 = blockIdx.x * BN;
    unsigned sbase = smem_u32(smc);

    const __half* B = BBase + (size_t)(m0 >> 11) * bStride;

    int wid = tid >> 5, lane = tid & 31;
    int wm = (wid & 1) * 64;
    int wn = (wid >> 1) * 32;

    float acc[4][4][4];
#pragma unroll
    for (int i = 0; i < 4; i++)
#pragma unroll
        for (int j = 0; j < 4; j++)
#pragma unroll
            for (int v = 0; v < 4; v++) acc[i][j][v] = 0.f;

    load_stage(sbase, tid, 0, A, B, m0, n0);
    CP_COMMIT();

    unsigned a_lo = (unsigned)((wm + (lane & 15)) * PK + ((lane >> 4) << 3)) * 2;
    unsigned b_lo = (unsigned)((wn + (lane & 15)) * PK + ((lane >> 4) << 3)) * 2;

    for (int it = 0; it < NIT; it++) {
        CP_WAIT(0);
        __syncthreads();
        if (it + 1 < NIT) {
            load_stage(sbase + (unsigned)((it + 1) & 1) * STAGEB, tid,
                       (it + 1) * BKE, A, B, m0, n0);
            CP_COMMIT();
        }

        unsigned sbuf = sbase + (unsigned)(it & 1) * STAGEB;
#pragma unroll
        for (int kk = 0; kk < 2; kk++) {
            unsigned ah[4][4], bb[2][4];
            unsigned ao = sbuf + a_lo + (unsigned)kk * 32;
            unsigned bo = sbuf + b_lo + (unsigned)kk * 32;

#pragma unroll
            for (int i = 0; i < 4; i++)
                LDSM4(ah[i][0], ah[i][1], ah[i][2], ah[i][3],
                      ao + (unsigned)i * (16 * PK * 2));
#pragma unroll
            for (int L = 0; L < 2; L++)
                LDSM4(bb[L][0], bb[L][1], bb[L][2], bb[L][3],
                      bo + TILEB + (unsigned)L * (16 * PK * 2));
#pragma unroll
            for (int i = 0; i < 4; i++)
#pragma unroll
                for (int j = 0; j < 4; j++) {
                    int L = j >> 1, s = j & 1;
                    MMAH(acc[i][j], ah[i], bb[L][s], bb[L][s + 2]);
                }
        }
    }

    // epilogue
    int r = lane >> 2, c2 = (lane & 3) * 2;
#pragma unroll
    for (int i = 0; i < 4; i++) {
        int m = m0 + wm + i * 16 + r;
#pragma unroll
        for (int j = 0; j < 4; j++) {
            int n = n0 + wn + j * 8 + c2;
            float bv0 = (n < N) ? bias[n] : 0.f;
            float bv1 = (n + 1 < N) ? bias[n + 1] : 0.f;
            float v00 = acc[i][j][0] * postScale + bv0;
            float v01 = acc[i][j][1] * postScale + bv1;
            float v10 = acc[i][j][2] * postScale + bv0;
            float v11 = acc[i][j][3] * postScale + bv1;
            if (C) {
                float* C0 = C + (size_t)m * N;
                float* C1 = C0 + (size_t)8 * N;
                if (n < N)     { C0[n] = v00; C1[n] = v10; }
                if (n + 1 < N) { C0[n + 1] = v01; C1[n + 1] = v11; }
            }
            if (Ph) {
                *(unsigned*)(Ph + (size_t)m * EMBED + n) =
                    h2bits(__floats2half2_rn(v00, v01));
                *(unsigned*)(Ph + (size_t)(m + 8) * EMBED + n) =
                    h2bits(__floats2half2_rn(v10, v11));
            }
        }
    }
}

// ---------- fp16 Gram: Gpart[chunk][bh] = P_h^T P_h over 128 s-rows ----------
// Operands are phh (fp16) — exact; fp32 accumulate. Single term.
#define GPD 72   // padded row (fp16): 144B -> conflict-free trans ldmatrix

__global__ __launch_bounds__(256, 4) void head_gram_fp16(
    const __half* __restrict__ ph, float* __restrict__ Gpart)
{
    __shared__ __half sh[128][GPD];

    int bh = blockIdx.x;               // 0..31
    int chunk = blockIdx.y;            // 0..15
    int b = bh >> 4;
    int h = bh & 15;
    int tid = threadIdx.x;
    int wid = tid >> 5, lane = tid & 31;
    int wm = (wid & 1) * 32;           // d1 offset
    int wn = (wid >> 1) * 16;          // d2 offset

    unsigned shB = smem_u32(&sh[0][0]);

    int g = lane >> 3, l = lane & 7;
    unsigned aRowOff = (unsigned)(((g & 2) ? 8 : 0) + l) * (GPD * 2);
    unsigned aColOff = (unsigned)(wm + ((g & 1) ? 8 : 0)) * 2;
    unsigned bRowOff = (unsigned)(((g & 1) ? 8 : 0) + l) * (GPD * 2);
    unsigned bColOff = (unsigned)(wn + ((g >= 2) ? 8 : 0)) * 2;

    float acc[2][2][4];
#pragma unroll
    for (int i = 0; i < 2; i++)
#pragma unroll
        for (int j = 0; j < 2; j++)
#pragma unroll
            for (int v = 0; v < 4; v++) acc[i][j][v] = 0.f;

    int row = tid >> 1;                 // 0..127
    int q = tid & 1;                    // 32-elem half
    unsigned soff = (unsigned)(row * GPD + q * 32) * 2;

    size_t gbase = (size_t)(b * SEQ + chunk * 128 + row) * EMBED + h * HDIM + q * 32;
#pragma unroll
    for (int t = 0; t < 4; t++)
        cpa16(shB + soff + t * 16, ph + gbase + t * 8);
    CP_COMMIT();
    CP_WAIT(0);
    __syncthreads();

#pragma unroll
    for (int k0 = 0; k0 < 128; k0 += 16) {
        unsigned kb = (unsigned)k0 * (GPD * 2);
        unsigned A2[2][4], B4[4];
#pragma unroll
        for (int i = 0; i < 2; i++)
            LDSM4T(A2[i][0], A2[i][1], A2[i][2], A2[i][3],
                   shB + kb + aRowOff + aColOff + (unsigned)i * 32);
        LDSM4T(B4[0], B4[1], B4[2], B4[3], shB + kb + bRowOff + bColOff);

#pragma unroll
        for (int i = 0; i < 2; i++)
#pragma unroll
            for (int j = 0; j < 2; j++)
                MMAH(acc[i][j], A2[i], B4[j * 2], B4[j * 2 + 1]);
    }

    float* Gp = Gpart + ((size_t)chunk * 32 + bh) * (HDIM * HDIM);
    int r = lane >> 2, c2 = (lane & 3) * 2;
#pragma unroll
    for (int i = 0; i < 2; i++) {
        int d1a = wm + i * 16 + r;
#pragma unroll
        for (int j = 0; j < 2; j++) {
            int d2 = wn + j * 8 + c2;
            Gp[d1a * HDIM + d2]           = acc[i][j][0];
            Gp[d1a * HDIM + d2 + 1]       = acc[i][j][1];
            Gp[(d1a + 8) * HDIM + d2]     = acc[i][j][2];
            Gp[(d1a + 8) * HDIM + d2 + 1] = acc[i][j][3];
        }
    }
}

__global__ void gram_reduce(const float* __restrict__ Gpart,
                            float* __restrict__ G, float scale)
{
    int idx = blockIdx.x * blockDim.x + threadIdx.x;
    if (idx >= 32 * HDIM * HDIM) return;
    float s = 0.f;
#pragma unroll
    for (int c = 0; c < GCHUNKS; c++)
        s += Gpart[(size_t)c * 32 * HDIM * HDIM + idx];
    G[idx] = s * scale;
}

// ---------- fused B2 build: fp16 hi only, pre-scaled ----------
__global__ __launch_bounds__(256) void w2_build(
    const float* __restrict__ Wo, const float* __restrict__ G,
    __half* __restrict__ B2h)
{
    int c0 = blockIdx.x * 64;
    int h  = blockIdx.y;
    int b  = blockIdx.z;
    const float* Gh = G + (size_t)(b * NHEADS + h) * HDIM * HDIM;

    __shared__ float Gs[64][65];
    __shared__ float Ws[64][65];
    int tid = threadIdx.x;

#pragma unroll
    for (int v = 0; v < 4; v++) {
        int idx = tid + v * 256;
        int rr = idx >> 4;
        int c = (idx & 15) << 2;
        float4 g4 = *(const float4*)(Gh + rr * HDIM + c);
        Gs[rr][c + 0] = g4.x; Gs[rr][c + 1] = g4.y;
        Gs[rr][c + 2] = g4.z; Gs[rr][c + 3] = g4.w;
        float4 w4 = make_float4(0.f, 0.f, 0.f, 0.f);
        if (c0 + rr < NCLS)
            w4 = *(const float4*)(Wo + (size_t)(c0 + rr) * EMBED + h * HDIM + c);
        Ws[rr][c + 0] = w4.x; Ws[rr][c + 1] = w4.y;
        Ws[rr][c + 2] = w4.z; Ws[rr][c + 3] = w4.w;
    }
    __syncthreads();

    int j  = tid & 63;
    int i0 = (tid >> 6) << 4;
    float acc[16];
#pragma unroll
    for (int ii = 0; ii < 16; ii++) acc[ii] = 0.f;

#pragma unroll 4
    for (int k = 0; k < 64; k++) {
        float g = Gs[k][j];
#pragma unroll
        for (int ii = 0; ii < 16; ii++)
            acc[ii] += Ws[i0 + ii][k] * g;
    }

#pragma unroll
    for (int ii = 0; ii < 16; ii++) {
        size_t o = (size_t)b * 1024 * EMBED + (size_t)(c0 + i0 + ii) * EMBED + h * HDIM + j;
        B2h[o] = __float2half_rn(acc[ii] * B2SCALE);
    }
}

// ---------- launch ----------
extern "C" void kernel_launch(void* const* d_in, const int* in_sizes, int n_in,
                              void* d_out, int out_size)
{
    const float* x     = (const float*)d_in[0];
    const float* W_in  = (const float*)d_in[1];
    const float* b_in  = (const float*)d_in[2];
    const float* W_out = (const float*)d_in[3];
    const float* b_out = (const float*)d_in[4];
    float* out = (float*)d_out;

    int M = in_sizes[0] / EMBED;   // 4096

    float *G, *Gp;
    cudaGetSymbolAddress((void**)&G, g_G);
    cudaGetSymbolAddress((void**)&Gp, g_Gpart);
    __half *xh, *wh, *phh, *b2h;
    cudaGetSymbolAddress((void**)&xh, g_xh);
    cudaGetSymbolAddress((void**)&wh, g_wh);
    cudaGetSymbolAddress((void**)&phh, g_phh);
    cudaGetSymbolAddress((void**)&b2h, g_b2h);

    cudaFuncSetAttribute(gemm_fp16, cudaFuncAttributeMaxDynamicSharedMemorySize, SMEM_BYTES);

    dim3 blk(256);

    // quantize: x -> fp16; W_in*32 -> fp16
    cvt_h<<<(M * EMBED / 4) / 256, blk>>>((const float4*)x, (uint2*)xh, M * EMBED / 4, 1.0f);
    cvt_h<<<(EMBED * EMBED / 4) / 256, blk>>>((const float4*)W_in, (uint2*)wh,
                                              EMBED * EMBED / 4, WSCALE);

    // 1) P = X @ W_in^T + b_in  (fp16 -> phh only)
    gemm_fp16<<<dim3(EMBED / BN, M / BM), blk, SMEM_BYTES>>>(
        xh, wh, b_in, 1.0f / WSCALE, nullptr, phh, EMBED, 0);

    // 2) G = (1/32) * phh_h^T phh_h  (fp16 operands exact; fp32 accum)
    head_gram_fp16<<<dim3(32, GCHUNKS), blk>>>(phh, Gp);
    gram_reduce<<<(32 * HDIM * HDIM + 255) / 256, blk>>>(Gp, G, 1.0f / 32.0f);

    // 3) B2[b] = blockdiag(G) @ W_out^T  (fp16, x16)
    w2_build<<<dim3(1024 / 64, NHEADS, M / SEQ), blk>>>(W_out, G, b2h);

    // 4) out = P @ B2[b]^T + b_out  (fp16)
    gemm_fp16<<<dim3(1024 / BN, M / BM), blk, SMEM_BYTES>>>(
        phh, b2h, b_out, 1.0f / B2SCALE, out, nullptr, NCLS, (long)1024 * EMBED);
}